// round 9
// baseline (speedup 1.0000x reference)
#include <cuda_runtime.h>
#include <math.h>

// Fixed problem shape
#define HH 128
#define GG 64
#define NN_MAX 100000
#define EE_MAX 1600000

typedef unsigned long long u64;
typedef unsigned int u32;

// Scratch: __device__ globals, referenced ONLY inside device code.
__device__ float g_h[NN_MAX * HH];
__device__ float g_aggr[NN_MAX * HH];
__device__ float g_tmp[NN_MAX * HH];
__device__ float g_pool[GG * HH];
__device__ float g_cnt[GG];
__device__ float g_st[GG * 64];
__device__ int   g_idx64;           // 1 if edge_index/batch are int64

// Pre-split tf32 weight planes: mats 0=W1L0, 1=W2L0, 2=W1L1, 3=W2L1
__device__ float g_Wh[4 * HH * HH];
__device__ float g_Wl[4 * HH * HH];

// CSR scratch (built once per call; graph shared by both layers)
__device__ int   g_deg[NN_MAX];
__device__ int   g_rowptr[NN_MAX + 1];
__device__ int   g_cursor[NN_MAX];
__device__ int   g_bsum[512];
__device__ int   g_boff[512];
__device__ int   g_esrc[EE_MAX];
__device__ float g_eea[EE_MAX];

#define BUF_AGGR 0
#define BUF_TMP  1
#define BUF_H    2
__device__ __forceinline__ float* buf_ptr(int sel) {
    return sel == BUF_AGGR ? g_aggr : (sel == BUF_TMP ? g_tmp : g_h);
}

__device__ __forceinline__ void red_add_v2(float* p, float a, float b) {
    asm volatile("red.global.add.v2.f32 [%0], {%1,%2};"
                 :: "l"(p), "f"(a), "f"(b) : "memory");
}

// tf32 helpers
__device__ __forceinline__ u32 f2tf32(float x) {
    u32 r; asm("cvt.rna.tf32.f32 %0, %1;" : "=r"(r) : "f"(x)); return r;
}
__device__ __forceinline__ void mma_tf32(float d[4], const u32 a[4],
                                         const u32 b[2]) {
    asm("mma.sync.aligned.m16n8k8.row.col.f32.tf32.tf32.f32 "
        "{%0,%1,%2,%3}, {%4,%5,%6,%7}, {%8,%9}, {%0,%1,%2,%3};"
        : "+f"(d[0]), "+f"(d[1]), "+f"(d[2]), "+f"(d[3])
        : "r"(a[0]), "r"(a[1]), "r"(a[2]), "r"(a[3]), "r"(b[0]), "r"(b[1]));
}

// ---------------------------------------------------------------------------
__global__ void detect_kernel(const void* ei_raw, int n) {
    if (threadIdx.x == 0 && blockIdx.x == 0) {
        const long long* p = (const long long*)ei_raw;
        int ok = 1;
        for (int i = 0; i < 16; i++) {
            long long v = p[i];
            if (v < 0 || v >= (long long)n) ok = 0;
        }
        g_idx64 = ok;
    }
}

// zero deg + pool + cnt in one pass
__global__ void zero_misc_kernel(int n) {
    int i = blockIdx.x * blockDim.x + threadIdx.x;
    if (i < n) g_deg[i] = 0;
    if (i < GG * HH) g_pool[i] = 0.0f;
    if (i < GG) g_cnt[i] = 0.0f;
}

// Pre-split W1/W2 (both layers) into tf32 hi/lo planes.
__global__ void presplit_kernel(const float* __restrict__ w1,
                                const float* __restrict__ w2) {
    int i = blockIdx.x * blockDim.x + threadIdx.x;   // 0 .. 2*HH*HH-1
    if (i >= 2 * HH * HH) return;
    int l = i >> 14;          // layer
    int off = i & 16383;
    float a = __ldg(w1 + i);
    float b = __ldg(w2 + i);
    u32 ahb = f2tf32(a); float ahf = __uint_as_float(ahb);
    u32 bhb = f2tf32(b); float bhf = __uint_as_float(bhb);
    int sa = (l * 2 + 0) * 16384 + off;
    int sb = (l * 2 + 1) * 16384 + off;
    g_Wh[sa] = ahf;
    g_Wl[sa] = __uint_as_float(f2tf32(a - ahf));
    g_Wh[sb] = bhf;
    g_Wl[sb] = __uint_as_float(f2tf32(b - bhf));
}

// ============================ CSR build (once) =============================
__global__ void csr_count_kernel(const void* __restrict__ ei_raw, int E, int n) {
    int e = blockIdx.x * blockDim.x + threadIdx.x;
    if (e >= E) return;
    long long dst;
    if (g_idx64) dst = __ldg((const long long*)ei_raw + E + e);
    else         dst = __ldg((const int*)ei_raw + E + e);
    if ((unsigned long long)dst >= (unsigned long long)n) return;
    atomicAdd(&g_deg[(int)dst], 1);
}

__global__ void blocksum_kernel(int n) {
    __shared__ int s[256];
    int t = threadIdx.x;
    int i = blockIdx.x * 256 + t;
    s[t] = (i < n) ? g_deg[i] : 0;
    __syncthreads();
    for (int d = 128; d > 0; d >>= 1) {
        if (t < d) s[t] += s[t + d];
        __syncthreads();
    }
    if (t == 0) g_bsum[blockIdx.x] = s[0];
}

__global__ void scan_bsum_kernel(int nb) {
    __shared__ int s[512];
    int t = threadIdx.x;
    int v0 = (t < nb) ? g_bsum[t] : 0;
    s[t] = v0;
    __syncthreads();
    for (int d = 1; d < 512; d <<= 1) {
        int v = (t >= d) ? s[t - d] : 0;
        __syncthreads();
        s[t] += v;
        __syncthreads();
    }
    g_boff[t] = s[t] - v0;
}

__global__ void rowptr_kernel(int n, int E) {
    __shared__ int s[256];
    int t = threadIdx.x;
    int i = blockIdx.x * 256 + t;
    int d = (i < n) ? g_deg[i] : 0;
    s[t] = d;
    __syncthreads();
    for (int dd = 1; dd < 256; dd <<= 1) {
        int v = (t >= dd) ? s[t - dd] : 0;
        __syncthreads();
        s[t] += v;
        __syncthreads();
    }
    int excl = s[t] - d + g_boff[blockIdx.x];
    if (i < n) {
        g_rowptr[i] = excl;
        g_cursor[i] = excl;
        if (i == n - 1) g_rowptr[n] = E;
    }
}

__global__ void csr_fill_kernel(const void* __restrict__ ei_raw,
                                const float* __restrict__ edge_attr,
                                int E, int n) {
    int e = blockIdx.x * blockDim.x + threadIdx.x;
    if (e >= E) return;
    long long src, dst;
    if (g_idx64) {
        const long long* ei = (const long long*)ei_raw;
        src = __ldg(ei + e);
        dst = __ldg(ei + E + e);
    } else {
        const int* ei = (const int*)ei_raw;
        src = __ldg(ei + e);
        dst = __ldg(ei + E + e);
    }
    if ((unsigned long long)src >= (unsigned long long)n ||
        (unsigned long long)dst >= (unsigned long long)n) return;
    int pos = atomicAdd(&g_cursor[(int)dst], 1);
    g_esrc[pos] = (int)src;
    g_eea[pos]  = __ldg(edge_attr + e);
}

// ==================== aggregate layer 0 (rank-1 h) ==========================
__global__ void aggregate_l0_kernel(const float* __restrict__ x,
                                    const float* __restrict__ enc_w,
                                    const float* __restrict__ enc_b,
                                    const float* __restrict__ edge_w,
                                    const float* __restrict__ edge_b,
                                    const float* __restrict__ eps0, int n) {
    int gt = blockIdx.x * blockDim.x + threadIdx.x;
    int i = gt >> 5;
    if (i >= n) return;
    int lane = gt & 31;
    int c = lane * 4;
    float4 cw = *(const float4*)(enc_w + c);
    float4 cb = *(const float4*)(enc_b + c);
    float4 ew = *(const float4*)(edge_w + c);
    float4 eb = *(const float4*)(edge_b + c);
    float4 mb;
    mb.x = cb.x + eb.x; mb.y = cb.y + eb.y;
    mb.z = cb.z + eb.z; mb.w = cb.w + eb.w;
    float s = 1.0f + __ldg(eps0);
    float xi = __ldg(x + i);
    float4 acc;
    acc.x = s * fmaf(xi, cw.x, cb.x);
    acc.y = s * fmaf(xi, cw.y, cb.y);
    acc.z = s * fmaf(xi, cw.z, cb.z);
    acc.w = s * fmaf(xi, cw.w, cb.w);

    int k0 = __ldg(&g_rowptr[i]);
    int k1 = __ldg(&g_rowptr[i + 1]);
    for (int k = k0; k < k1; k++) {
        float xs = __ldg(x + __ldg(&g_esrc[k]));
        float ea = __ldg(&g_eea[k]);
        acc.x += fmaxf(fmaf(xs, cw.x, fmaf(ea, ew.x, mb.x)), 0.0f);
        acc.y += fmaxf(fmaf(xs, cw.y, fmaf(ea, ew.y, mb.y)), 0.0f);
        acc.z += fmaxf(fmaf(xs, cw.z, fmaf(ea, ew.z, mb.z)), 0.0f);
        acc.w += fmaxf(fmaf(xs, cw.w, fmaf(ea, ew.w, mb.w)), 0.0f);
    }
    *(float4*)(g_aggr + (size_t)i * HH + c) = acc;
}

// ==================== aggregate layer 1 (dense h gather) ====================
// One warp per node, unroll-8 edge prefetch for memory-level parallelism.
__global__ void aggregate_kernel(const float* __restrict__ edge_w,
                                 const float* __restrict__ edge_b,
                                 const float* __restrict__ eps_l, int n) {
    int gt = blockIdx.x * blockDim.x + threadIdx.x;
    int i = gt >> 5;
    if (i >= n) return;
    int lane = gt & 31;
    int c = lane * 4;
    float4 ew = *(const float4*)(edge_w + c);
    float4 eb = *(const float4*)(edge_b + c);
    float s = 1.0f + __ldg(eps_l);

    float4 hv = *(const float4*)(g_h + (size_t)i * HH + c);
    float4 acc;
    acc.x = hv.x * s; acc.y = hv.y * s; acc.z = hv.z * s; acc.w = hv.w * s;

    int k0 = __ldg(&g_rowptr[i]);
    int k1 = __ldg(&g_rowptr[i + 1]);
    int k = k0;
    for (; k + 8 <= k1; k += 8) {
        int si[8]; float ai[8]; float4 vv[8];
        #pragma unroll
        for (int u = 0; u < 8; u++) si[u] = __ldg(&g_esrc[k + u]);
        #pragma unroll
        for (int u = 0; u < 8; u++) ai[u] = __ldg(&g_eea[k + u]);
        #pragma unroll
        for (int u = 0; u < 8; u++)
            vv[u] = *(const float4*)(g_h + (size_t)si[u] * HH + c);
        #pragma unroll
        for (int u = 0; u < 8; u++) {
            acc.x += fmaxf(vv[u].x + fmaf(ai[u], ew.x, eb.x), 0.0f);
            acc.y += fmaxf(vv[u].y + fmaf(ai[u], ew.y, eb.y), 0.0f);
            acc.z += fmaxf(vv[u].z + fmaf(ai[u], ew.z, eb.z), 0.0f);
            acc.w += fmaxf(vv[u].w + fmaf(ai[u], ew.w, eb.w), 0.0f);
        }
    }
    for (; k < k1; k++) {
        int src = __ldg(&g_esrc[k]);
        float ea = __ldg(&g_eea[k]);
        float4 sv = *(const float4*)(g_h + (size_t)src * HH + c);
        acc.x += fmaxf(sv.x + fmaf(ea, ew.x, eb.x), 0.0f);
        acc.y += fmaxf(sv.y + fmaf(ea, ew.y, eb.y), 0.0f);
        acc.z += fmaxf(sv.z + fmaf(ea, ew.z, eb.z), 0.0f);
        acc.w += fmaxf(sv.w + fmaf(ea, ew.w, eb.w), 0.0f);
    }
    *(float4*)(g_aggr + (size_t)i * HH + c) = acc;
}

// ---------------------------------------------------------------------------
// Tensor-core GEMM (3xTF32): C[M,128] = act(A[M,128] @ W[128,128] + bias).
// W comes pre-split from g_Wh/g_Wl (WIDX selects the matrix) -> fill is pure
// vector copy. A split on the fly with float4 loads.
#define BK 16
#define SWS 136
template <int MODE, int SRC, int DST, int POOL, int WIDX>
__global__ void __launch_bounds__(256, 2)
gemm128_kernel(const float* __restrict__ bias,
               const float* __restrict__ bn_g,
               const float* __restrict__ bn_b,
               const float* __restrict__ bn_m,
               const float* __restrict__ bn_v,
               const void* __restrict__ batch_raw,
               int M) {
    const float* A = buf_ptr(SRC);
    float*       C = buf_ptr(DST);
    const float* Wh = g_Wh + WIDX * (HH * HH);
    const float* Wl = g_Wl + WIDX * (HH * HH);

    __shared__ float sAh[BK * SWS], sAl[BK * SWS];
    __shared__ float sWh[BK * SWS], sWl[BK * SWS];

    int tid = threadIdx.x;
    int lane = tid & 31;
    int wid = tid >> 5;
    int g = lane >> 2;
    int tig = lane & 3;
    int wr = wid >> 2;
    int wc = wid & 3;
    int row0 = blockIdx.x * 128;

    float d[4][4][4];
    #pragma unroll
    for (int i = 0; i < 4; i++)
        #pragma unroll
        for (int j = 0; j < 4; j++)
            #pragma unroll
            for (int r = 0; r < 4; r++) d[i][j][r] = 0.0f;

    for (int k0 = 0; k0 < HH; k0 += BK) {
        __syncthreads();
        // W chunk fill: pure float4 copy from pre-split planes
        #pragma unroll
        for (int s = 0; s < 2; s++) {
            int e = tid + s * 256;          // 0..511 float4 groups
            int kk = e >> 5;
            int c4 = (e & 31) * 4;
            const float4* ph = (const float4*)(Wh + (size_t)(k0 + kk) * HH + c4);
            const float4* pl = (const float4*)(Wl + (size_t)(k0 + kk) * HH + c4);
            *(float4*)(sWh + kk * SWS + c4) = *ph;
            *(float4*)(sWl + kk * SWS + c4) = *pl;
        }
        // A chunk fill: float4 loads (4 k of one row), split, transposed stores
        #pragma unroll
        for (int s = 0; s < 2; s++) {
            int e = tid + s * 256;          // 0..511
            int r  = e >> 2;
            int kq = (e & 3) * 4;
            int grow = row0 + r;
            float4 a4 = (grow < M)
                ? *(const float4*)(A + (size_t)grow * HH + k0 + kq)
                : make_float4(0.f, 0.f, 0.f, 0.f);
            float av[4] = {a4.x, a4.y, a4.z, a4.w};
            #pragma unroll
            for (int j = 0; j < 4; j++) {
                u32 hb = f2tf32(av[j]);
                float hf = __uint_as_float(hb);
                sAh[(kq + j) * SWS + r] = hf;
                sAl[(kq + j) * SWS + r] = __uint_as_float(f2tf32(av[j] - hf));
            }
        }
        __syncthreads();

        #pragma unroll
        for (int ks = 0; ks < 2; ks++) {
            int kb = ks * 8;
            u32 bh[4][2], bl[4][2];
            #pragma unroll
            for (int nt = 0; nt < 4; nt++) {
                int cc = wc * 32 + nt * 8 + g;
                bh[nt][0] = __float_as_uint(sWh[(kb + tig) * SWS + cc]);
                bh[nt][1] = __float_as_uint(sWh[(kb + tig + 4) * SWS + cc]);
                bl[nt][0] = __float_as_uint(sWl[(kb + tig) * SWS + cc]);
                bl[nt][1] = __float_as_uint(sWl[(kb + tig + 4) * SWS + cc]);
            }
            #pragma unroll
            for (int mt = 0; mt < 4; mt++) {
                int rr = wr * 64 + mt * 16 + g;
                u32 ah[4], al[4];
                ah[0] = __float_as_uint(sAh[(kb + tig) * SWS + rr]);
                ah[1] = __float_as_uint(sAh[(kb + tig) * SWS + rr + 8]);
                ah[2] = __float_as_uint(sAh[(kb + tig + 4) * SWS + rr]);
                ah[3] = __float_as_uint(sAh[(kb + tig + 4) * SWS + rr + 8]);
                al[0] = __float_as_uint(sAl[(kb + tig) * SWS + rr]);
                al[1] = __float_as_uint(sAl[(kb + tig) * SWS + rr + 8]);
                al[2] = __float_as_uint(sAl[(kb + tig + 4) * SWS + rr]);
                al[3] = __float_as_uint(sAl[(kb + tig + 4) * SWS + rr + 8]);
                #pragma unroll
                for (int nt = 0; nt < 4; nt++) {
                    mma_tf32(d[mt][nt], ah, bh[nt]);
                    mma_tf32(d[mt][nt], ah, bl[nt]);
                    mma_tf32(d[mt][nt], al, bh[nt]);
                }
            }
        }
    }

    float2 bb[4], ssv[4], ttv[4];
    #pragma unroll
    for (int nt = 0; nt < 4; nt++) {
        int c = wc * 32 + nt * 8 + 2 * tig;
        bb[nt] = *(const float2*)(bias + c);
        if (MODE == 1) {
            float2 bv = *(const float2*)(bn_v + c);
            float2 bg = *(const float2*)(bn_g + c);
            float2 bm = *(const float2*)(bn_m + c);
            float2 bbeta = *(const float2*)(bn_b + c);
            float i0 = rsqrtf(fabsf(bv.x) + 1e-5f);
            float i1 = rsqrtf(fabsf(bv.y) + 1e-5f);
            ssv[nt].x = bg.x * i0;
            ssv[nt].y = bg.y * i1;
            ttv[nt].x = bbeta.x - bm.x * ssv[nt].x;
            ttv[nt].y = bbeta.y - bm.y * ssv[nt].y;
        }
    }

    #pragma unroll
    for (int mt = 0; mt < 4; mt++) {
        int r0 = row0 + wr * 64 + mt * 16 + g;
        int r1 = r0 + 8;
        long long b0 = 0, b1 = 0;
        if (POOL) {
            if (g_idx64) {
                if (r0 < M) b0 = __ldg((const long long*)batch_raw + r0);
                if (r1 < M) b1 = __ldg((const long long*)batch_raw + r1);
            } else {
                if (r0 < M) b0 = __ldg((const int*)batch_raw + r0);
                if (r1 < M) b1 = __ldg((const int*)batch_raw + r1);
            }
        }
        #pragma unroll
        for (int nt = 0; nt < 4; nt++) {
            int c = wc * 32 + nt * 8 + 2 * tig;
            float z0 = d[mt][nt][0] + bb[nt].x;
            float z1 = d[mt][nt][1] + bb[nt].y;
            float z2 = d[mt][nt][2] + bb[nt].x;
            float z3 = d[mt][nt][3] + bb[nt].y;
            if (MODE == 1) {
                z0 = fmaf(z0, ssv[nt].x, ttv[nt].x);
                z1 = fmaf(z1, ssv[nt].y, ttv[nt].y);
                z2 = fmaf(z2, ssv[nt].x, ttv[nt].x);
                z3 = fmaf(z3, ssv[nt].y, ttv[nt].y);
            }
            z0 = fmaxf(z0, 0.0f); z1 = fmaxf(z1, 0.0f);
            z2 = fmaxf(z2, 0.0f); z3 = fmaxf(z3, 0.0f);
            if (POOL) {
                if (r0 < M && (unsigned long long)b0 < (unsigned long long)GG)
                    red_add_v2(g_pool + (size_t)b0 * HH + c, z0, z1);
                if (r1 < M && (unsigned long long)b1 < (unsigned long long)GG)
                    red_add_v2(g_pool + (size_t)b1 * HH + c, z2, z3);
            } else {
                if (r0 < M)
                    *(float2*)(C + (size_t)r0 * HH + c) = make_float2(z0, z1);
                if (r1 < M)
                    *(float2*)(C + (size_t)r1 * HH + c) = make_float2(z2, z3);
            }
        }
    }
}

// ---------------------------------------------------------------------------
__global__ void cnt_kernel(const void* __restrict__ batch_raw, int n) {
    int i = blockIdx.x * blockDim.x + threadIdx.x;
    if (i >= n) return;
    long long b;
    if (g_idx64) b = __ldg((const long long*)batch_raw + i);
    else         b = __ldg((const int*)batch_raw + i);
    if ((unsigned long long)b < (unsigned long long)GG)
        atomicAdd(&g_cnt[b], 1.0f);
}

// ---------------------------------------------------------------------------
__global__ void classifier1_kernel(const float* __restrict__ cls_w1,
                                   const float* __restrict__ cls_b1) {
    __shared__ float sg[GG * HH];
    int tid = threadIdx.x;
    for (int i = tid; i < GG * HH; i += 256) {
        float cnt = g_cnt[i >> 7];
        sg[i] = g_pool[i] / fmaxf(cnt, 1.0f);
    }
    __syncthreads();
    for (int e = tid; e < GG * 64; e += 256) {
        int gi = e >> 6;
        int m  = e & 63;
        float s = cls_b1[m];
        #pragma unroll 8
        for (int k = 0; k < HH; k++)
            s = fmaf(sg[gi * HH + k], cls_w1[k * 64 + m], s);
        g_st[e] = fmaxf(s, 0.0f);
    }
}

__global__ void classifier2_kernel(const float* __restrict__ cls_w2,
                                   const float* __restrict__ cls_b2,
                                   float* __restrict__ out) {
    int g = threadIdx.x;
    if (g < GG) {
        float s = cls_b2[0];
        #pragma unroll 8
        for (int m = 0; m < 64; m++)
            s = fmaf(g_st[g * 64 + m], cls_w2[m], s);
        out[g] = 1.0f / (1.0f + expf(-s));
    }
}

// ---------------------------------------------------------------------------
extern "C" void kernel_launch(void* const* d_in, const int* in_sizes, int n_in,
                              void* d_out, int out_size) {
    const float *x, *edge_attr, *enc_w, *enc_b, *edge_w, *edge_b, *eps;
    const float *mlp_w1, *mlp_b1, *mlp_w2, *mlp_b2;
    const float *bn_gamma, *bn_beta, *bn_mean, *bn_var;
    const float *cls_w1, *cls_b1, *cls_w2, *cls_b2;
    const void *edge_index, *batch;
    int n, E;

    if (in_sizes[1] > 1000) {
        x          = (const float*)d_in[0];
        edge_index = d_in[1];
        edge_attr  = (const float*)d_in[2];
        batch      = d_in[3];
        enc_w      = (const float*)d_in[4];
        enc_b      = (const float*)d_in[5];
        edge_w     = (const float*)d_in[6];
        edge_b     = (const float*)d_in[7];
        eps        = (const float*)d_in[8];
        mlp_w1     = (const float*)d_in[9];
        mlp_b1     = (const float*)d_in[10];
        mlp_w2     = (const float*)d_in[11];
        mlp_b2     = (const float*)d_in[12];
        bn_gamma   = (const float*)d_in[13];
        bn_beta    = (const float*)d_in[14];
        bn_mean    = (const float*)d_in[15];
        bn_var     = (const float*)d_in[16];
        cls_w1     = (const float*)d_in[17];
        cls_b1     = (const float*)d_in[18];
        cls_w2     = (const float*)d_in[19];
        cls_b2     = (const float*)d_in[20];
        n = in_sizes[0];
        E = in_sizes[2];
    } else {
        batch      = d_in[0];
        bn_beta    = (const float*)d_in[1];
        bn_gamma   = (const float*)d_in[2];
        bn_mean    = (const float*)d_in[3];
        bn_var     = (const float*)d_in[4];
        cls_b1     = (const float*)d_in[5];
        cls_b2     = (const float*)d_in[6];
        cls_w1     = (const float*)d_in[7];
        cls_w2     = (const float*)d_in[8];
        edge_attr  = (const float*)d_in[9];
        edge_b     = (const float*)d_in[10];
        edge_index = d_in[11];
        edge_w     = (const float*)d_in[12];
        enc_b      = (const float*)d_in[13];
        enc_w      = (const float*)d_in[14];
        eps        = (const float*)d_in[15];
        mlp_b1     = (const float*)d_in[16];
        mlp_b2     = (const float*)d_in[17];
        mlp_w1     = (const float*)d_in[18];
        mlp_w2     = (const float*)d_in[19];
        x          = (const float*)d_in[20];
        n = in_sizes[20];
        E = in_sizes[9];
    }
    float* out = (float*)d_out;
    if (E > EE_MAX) E = EE_MAX;

    int nblk = (n + 255) / 256;

    // 0) init (detect must precede anything reading g_idx64)
    detect_kernel<<<1, 32>>>(edge_index, n);
    zero_misc_kernel<<<nblk, 256>>>(n);
    presplit_kernel<<<(2 * HH * HH + 255) / 256, 256>>>(mlp_w1, mlp_w2);

    // 1) CSR build (launch #4 = csr_count -> profiled)
    csr_count_kernel<<<(E + 255) / 256, 256>>>(edge_index, E, n);
    blocksum_kernel<<<nblk, 256>>>(n);
    scan_bsum_kernel<<<1, 512>>>(nblk);
    rowptr_kernel<<<nblk, 256>>>(n, E);
    csr_fill_kernel<<<(E + 255) / 256, 256>>>(edge_index, edge_attr, E, n);

    // 2) layers
    int gemm_blocks = (n + 127) / 128;
    int agg_blocks = (n * 32 + 255) / 256;

    aggregate_l0_kernel<<<agg_blocks, 256>>>(x, enc_w, enc_b, edge_w, edge_b,
                                             eps, n);
    gemm128_kernel<0, BUF_AGGR, BUF_TMP, 0, 0><<<gemm_blocks, 256>>>(
        mlp_b1, nullptr, nullptr, nullptr, nullptr, nullptr, n);
    gemm128_kernel<1, BUF_TMP, BUF_H, 0, 1><<<gemm_blocks, 256>>>(
        mlp_b2, bn_gamma, bn_beta, bn_mean, bn_var, nullptr, n);

    aggregate_kernel<<<agg_blocks, 256>>>(edge_w, edge_b, eps + 1, n);
    gemm128_kernel<0, BUF_AGGR, BUF_TMP, 0, 2><<<gemm_blocks, 256>>>(
        mlp_b1 + HH, nullptr, nullptr, nullptr, nullptr, nullptr, n);
    gemm128_kernel<1, BUF_TMP, BUF_H, 1, 3><<<gemm_blocks, 256>>>(
        mlp_b2 + HH, bn_gamma + HH, bn_beta + HH, bn_mean + HH, bn_var + HH,
        batch, n);

    // 3) counts + classifier
    cnt_kernel<<<nblk, 256>>>(batch, n);
    classifier1_kernel<<<1, 256>>>(cls_w1, cls_b1);
    classifier2_kernel<<<1, 64>>>(cls_w2, cls_b2, out);
}

// round 10
// speedup vs baseline: 1.3061x; 1.3061x over previous
#include <cuda_runtime.h>
#include <cuda_bf16.h>
#include <math.h>

// Fixed problem shape
#define HH 128
#define GG 64
#define NN_MAX 100000
#define EE_MAX 1600000

typedef unsigned long long u64;
typedef unsigned int u32;

// Scratch: __device__ globals, referenced ONLY inside device code.
__device__ __nv_bfloat16 g_hb[NN_MAX * HH];   // node features (bf16)
__device__ float g_aggr[NN_MAX * HH];
__device__ float g_tmp[NN_MAX * HH];
__device__ float g_pool[GG * HH];
__device__ float g_cnt[GG];
__device__ float g_st[GG * 64];
__device__ int   g_idx64;           // 1 if edge_index/batch are int64

// Pre-converted tf32 weights: mats 0=W1L0, 1=W2L0, 2=W1L1, 3=W2L1
__device__ float g_Wh[4 * HH * HH];

// CSR scratch (built once per call; graph shared by both layers)
__device__ int   g_deg[NN_MAX];
__device__ int   g_rowptr[NN_MAX + 1];
__device__ int   g_cursor[NN_MAX];
__device__ int   g_bsum[512];
__device__ int   g_boff[512];
__device__ int   g_esrc[EE_MAX];
__device__ float g_eea[EE_MAX];

__device__ __forceinline__ void red_add_v2(float* p, float a, float b) {
    asm volatile("red.global.add.v2.f32 [%0], {%1,%2};"
                 :: "l"(p), "f"(a), "f"(b) : "memory");
}

// tf32 helpers
__device__ __forceinline__ u32 f2tf32(float x) {
    u32 r; asm("cvt.rna.tf32.f32 %0, %1;" : "=r"(r) : "f"(x)); return r;
}
__device__ __forceinline__ void mma_tf32(float d[4], const u32 a[4],
                                         const u32 b[2]) {
    asm("mma.sync.aligned.m16n8k8.row.col.f32.tf32.tf32.f32 "
        "{%0,%1,%2,%3}, {%4,%5,%6,%7}, {%8,%9}, {%0,%1,%2,%3};"
        : "+f"(d[0]), "+f"(d[1]), "+f"(d[2]), "+f"(d[3])
        : "r"(a[0]), "r"(a[1]), "r"(a[2]), "r"(a[3]), "r"(b[0]), "r"(b[1]));
}

// ---------------------------------------------------------------------------
__global__ void detect_kernel(const void* ei_raw, int n) {
    if (threadIdx.x == 0 && blockIdx.x == 0) {
        const long long* p = (const long long*)ei_raw;
        int ok = 1;
        for (int i = 0; i < 16; i++) {
            long long v = p[i];
            if (v < 0 || v >= (long long)n) ok = 0;
        }
        g_idx64 = ok;
    }
}

// zero deg + pool + cnt in one pass
__global__ void zero_misc_kernel(int n) {
    int i = blockIdx.x * blockDim.x + threadIdx.x;
    if (i < n) g_deg[i] = 0;
    if (i < GG * HH) g_pool[i] = 0.0f;
    if (i < GG) g_cnt[i] = 0.0f;
}

// Pre-convert W1/W2 (both layers) to tf32.
__global__ void presplit_kernel(const float* __restrict__ w1,
                                const float* __restrict__ w2) {
    int i = blockIdx.x * blockDim.x + threadIdx.x;   // 0 .. 2*HH*HH-1
    if (i >= 2 * HH * HH) return;
    int l = i >> 14;
    int off = i & 16383;
    g_Wh[(l * 2 + 0) * 16384 + off] = __uint_as_float(f2tf32(__ldg(w1 + i)));
    g_Wh[(l * 2 + 1) * 16384 + off] = __uint_as_float(f2tf32(__ldg(w2 + i)));
}

// ============================ CSR build (once) =============================
__global__ void csr_count_kernel(const void* __restrict__ ei_raw, int E, int n) {
    int e = blockIdx.x * blockDim.x + threadIdx.x;
    if (e >= E) return;
    long long dst;
    if (g_idx64) dst = __ldg((const long long*)ei_raw + E + e);
    else         dst = __ldg((const int*)ei_raw + E + e);
    if ((unsigned long long)dst >= (unsigned long long)n) return;
    atomicAdd(&g_deg[(int)dst], 1);
}

__global__ void blocksum_kernel(int n) {
    __shared__ int s[256];
    int t = threadIdx.x;
    int i = blockIdx.x * 256 + t;
    s[t] = (i < n) ? g_deg[i] : 0;
    __syncthreads();
    for (int d = 128; d > 0; d >>= 1) {
        if (t < d) s[t] += s[t + d];
        __syncthreads();
    }
    if (t == 0) g_bsum[blockIdx.x] = s[0];
}

__global__ void scan_bsum_kernel(int nb) {
    __shared__ int s[512];
    int t = threadIdx.x;
    int v0 = (t < nb) ? g_bsum[t] : 0;
    s[t] = v0;
    __syncthreads();
    for (int d = 1; d < 512; d <<= 1) {
        int v = (t >= d) ? s[t - d] : 0;
        __syncthreads();
        s[t] += v;
        __syncthreads();
    }
    g_boff[t] = s[t] - v0;
}

__global__ void rowptr_kernel(int n, int E) {
    __shared__ int s[256];
    int t = threadIdx.x;
    int i = blockIdx.x * 256 + t;
    int d = (i < n) ? g_deg[i] : 0;
    s[t] = d;
    __syncthreads();
    for (int dd = 1; dd < 256; dd <<= 1) {
        int v = (t >= dd) ? s[t - dd] : 0;
        __syncthreads();
        s[t] += v;
        __syncthreads();
    }
    int excl = s[t] - d + g_boff[blockIdx.x];
    if (i < n) {
        g_rowptr[i] = excl;
        g_cursor[i] = excl;
        if (i == n - 1) g_rowptr[n] = E;
    }
}

__global__ void csr_fill_kernel(const void* __restrict__ ei_raw,
                                const float* __restrict__ edge_attr,
                                int E, int n) {
    int e = blockIdx.x * blockDim.x + threadIdx.x;
    if (e >= E) return;
    long long src, dst;
    if (g_idx64) {
        const long long* ei = (const long long*)ei_raw;
        src = __ldg(ei + e);
        dst = __ldg(ei + E + e);
    } else {
        const int* ei = (const int*)ei_raw;
        src = __ldg(ei + e);
        dst = __ldg(ei + E + e);
    }
    if ((unsigned long long)src >= (unsigned long long)n ||
        (unsigned long long)dst >= (unsigned long long)n) return;
    int pos = atomicAdd(&g_cursor[(int)dst], 1);
    g_esrc[pos] = (int)src;
    g_eea[pos]  = __ldg(edge_attr + e);
}

// ==================== aggregate layer 0 (rank-1 h) ==========================
__global__ void aggregate_l0_kernel(const float* __restrict__ x,
                                    const float* __restrict__ enc_w,
                                    const float* __restrict__ enc_b,
                                    const float* __restrict__ edge_w,
                                    const float* __restrict__ edge_b,
                                    const float* __restrict__ eps0, int n) {
    int gt = blockIdx.x * blockDim.x + threadIdx.x;
    int i = gt >> 5;
    if (i >= n) return;
    int lane = gt & 31;
    int c = lane * 4;
    float4 cw = *(const float4*)(enc_w + c);
    float4 cb = *(const float4*)(enc_b + c);
    float4 ew = *(const float4*)(edge_w + c);
    float4 eb = *(const float4*)(edge_b + c);
    float4 mb;
    mb.x = cb.x + eb.x; mb.y = cb.y + eb.y;
    mb.z = cb.z + eb.z; mb.w = cb.w + eb.w;
    float s = 1.0f + __ldg(eps0);
    float xi = __ldg(x + i);
    float4 acc;
    acc.x = s * fmaf(xi, cw.x, cb.x);
    acc.y = s * fmaf(xi, cw.y, cb.y);
    acc.z = s * fmaf(xi, cw.z, cb.z);
    acc.w = s * fmaf(xi, cw.w, cb.w);

    int k0 = __ldg(&g_rowptr[i]);
    int k1 = __ldg(&g_rowptr[i + 1]);
    for (int k = k0; k < k1; k++) {
        float xs = __ldg(x + __ldg(&g_esrc[k]));
        float ea = __ldg(&g_eea[k]);
        acc.x += fmaxf(fmaf(xs, cw.x, fmaf(ea, ew.x, mb.x)), 0.0f);
        acc.y += fmaxf(fmaf(xs, cw.y, fmaf(ea, ew.y, mb.y)), 0.0f);
        acc.z += fmaxf(fmaf(xs, cw.z, fmaf(ea, ew.z, mb.z)), 0.0f);
        acc.w += fmaxf(fmaf(xs, cw.w, fmaf(ea, ew.w, mb.w)), 0.0f);
    }
    *(float4*)(g_aggr + (size_t)i * HH + c) = acc;
}

// ==================== aggregate layer 1 (bf16 h gather) =====================
__device__ __forceinline__ float4 ldhb4(const __nv_bfloat16* p) {
    uint2 rv = *(const uint2*)p;
    __nv_bfloat162 b0 = *reinterpret_cast<__nv_bfloat162*>(&rv.x);
    __nv_bfloat162 b1 = *reinterpret_cast<__nv_bfloat162*>(&rv.y);
    float2 f0 = __bfloat1622float2(b0);
    float2 f1 = __bfloat1622float2(b1);
    return make_float4(f0.x, f0.y, f1.x, f1.y);
}

__global__ void aggregate_kernel(const float* __restrict__ edge_w,
                                 const float* __restrict__ edge_b,
                                 const float* __restrict__ eps_l, int n) {
    int gt = blockIdx.x * blockDim.x + threadIdx.x;
    int i = gt >> 5;
    if (i >= n) return;
    int lane = gt & 31;
    int c = lane * 4;
    float4 ew = *(const float4*)(edge_w + c);
    float4 eb = *(const float4*)(edge_b + c);
    float s = 1.0f + __ldg(eps_l);

    float4 hv = ldhb4(g_hb + (size_t)i * HH + c);
    float4 acc;
    acc.x = hv.x * s; acc.y = hv.y * s; acc.z = hv.z * s; acc.w = hv.w * s;

    int k0 = __ldg(&g_rowptr[i]);
    int k1 = __ldg(&g_rowptr[i + 1]);
    int k = k0;
    for (; k + 8 <= k1; k += 8) {
        int si[8]; float ai[8]; float4 vv[8];
        #pragma unroll
        for (int u = 0; u < 8; u++) si[u] = __ldg(&g_esrc[k + u]);
        #pragma unroll
        for (int u = 0; u < 8; u++) ai[u] = __ldg(&g_eea[k + u]);
        #pragma unroll
        for (int u = 0; u < 8; u++)
            vv[u] = ldhb4(g_hb + (size_t)si[u] * HH + c);
        #pragma unroll
        for (int u = 0; u < 8; u++) {
            acc.x += fmaxf(vv[u].x + fmaf(ai[u], ew.x, eb.x), 0.0f);
            acc.y += fmaxf(vv[u].y + fmaf(ai[u], ew.y, eb.y), 0.0f);
            acc.z += fmaxf(vv[u].z + fmaf(ai[u], ew.z, eb.z), 0.0f);
            acc.w += fmaxf(vv[u].w + fmaf(ai[u], ew.w, eb.w), 0.0f);
        }
    }
    for (; k < k1; k++) {
        int src = __ldg(&g_esrc[k]);
        float ea = __ldg(&g_eea[k]);
        float4 sv = ldhb4(g_hb + (size_t)src * HH + c);
        acc.x += fmaxf(sv.x + fmaf(ea, ew.x, eb.x), 0.0f);
        acc.y += fmaxf(sv.y + fmaf(ea, ew.y, eb.y), 0.0f);
        acc.z += fmaxf(sv.z + fmaf(ea, ew.z, eb.z), 0.0f);
        acc.w += fmaxf(sv.w + fmaf(ea, ew.w, eb.w), 0.0f);
    }
    *(float4*)(g_aggr + (size_t)i * HH + c) = acc;
}

// ---------------------------------------------------------------------------
// Tensor-core GEMM (single-pass TF32): C = act(A @ W + bias).
// MODE 0: bias+relu. MODE 1: bias+BN+relu.
// OUTK 0: fp32 store to g_tmp. OUTK 1: bf16 store to g_hb. OUTK 2: pool red.
// SRC 0: g_aggr, 1: g_tmp. WIDX selects pre-converted tf32 weight matrix.
#define BK 16
#define SWS 136
template <int MODE, int OUTK, int SRC, int WIDX>
__global__ void __launch_bounds__(256, 2)
gemm128_kernel(const float* __restrict__ bias,
               const float* __restrict__ bn_g,
               const float* __restrict__ bn_b,
               const float* __restrict__ bn_m,
               const float* __restrict__ bn_v,
               const void* __restrict__ batch_raw,
               int M) {
    const float* A = SRC == 0 ? g_aggr : g_tmp;
    const float* Wh = g_Wh + WIDX * (HH * HH);

    __shared__ float sAh[BK * SWS];
    __shared__ float sWh[BK * SWS];

    int tid = threadIdx.x;
    int lane = tid & 31;
    int wid = tid >> 5;
    int g = lane >> 2;
    int tig = lane & 3;
    int wr = wid >> 2;
    int wc = wid & 3;
    int row0 = blockIdx.x * 128;

    float d[4][4][4];
    #pragma unroll
    for (int i = 0; i < 4; i++)
        #pragma unroll
        for (int j = 0; j < 4; j++)
            #pragma unroll
            for (int r = 0; r < 4; r++) d[i][j][r] = 0.0f;

    for (int k0 = 0; k0 < HH; k0 += BK) {
        __syncthreads();
        // W chunk: float4 copy from pre-converted tf32 plane
        {
            int e = tid;                       // 512 float4 groups / 256 thr
            #pragma unroll
            for (int s = 0; s < 2; s++, e += 256) {
                int kk = e >> 5;
                int c4 = (e & 31) * 4;
                *(float4*)(sWh + kk * SWS + c4) =
                    *(const float4*)(Wh + (size_t)(k0 + kk) * HH + c4);
            }
        }
        // A chunk: float4 loads, cvt to tf32, transposed stores
        {
            int e = tid;
            #pragma unroll
            for (int s = 0; s < 2; s++, e += 256) {
                int r  = e >> 2;
                int kq = (e & 3) * 4;
                int grow = row0 + r;
                float4 a4 = (grow < M)
                    ? *(const float4*)(A + (size_t)grow * HH + k0 + kq)
                    : make_float4(0.f, 0.f, 0.f, 0.f);
                sAh[(kq + 0) * SWS + r] = __uint_as_float(f2tf32(a4.x));
                sAh[(kq + 1) * SWS + r] = __uint_as_float(f2tf32(a4.y));
                sAh[(kq + 2) * SWS + r] = __uint_as_float(f2tf32(a4.z));
                sAh[(kq + 3) * SWS + r] = __uint_as_float(f2tf32(a4.w));
            }
        }
        __syncthreads();

        #pragma unroll
        for (int ks = 0; ks < 2; ks++) {
            int kb = ks * 8;
            u32 bh[4][2];
            #pragma unroll
            for (int nt = 0; nt < 4; nt++) {
                int cc = wc * 32 + nt * 8 + g;
                bh[nt][0] = __float_as_uint(sWh[(kb + tig) * SWS + cc]);
                bh[nt][1] = __float_as_uint(sWh[(kb + tig + 4) * SWS + cc]);
            }
            #pragma unroll
            for (int mt = 0; mt < 4; mt++) {
                int rr = wr * 64 + mt * 16 + g;
                u32 ah[4];
                ah[0] = __float_as_uint(sAh[(kb + tig) * SWS + rr]);
                ah[1] = __float_as_uint(sAh[(kb + tig) * SWS + rr + 8]);
                ah[2] = __float_as_uint(sAh[(kb + tig + 4) * SWS + rr]);
                ah[3] = __float_as_uint(sAh[(kb + tig + 4) * SWS + rr + 8]);
                #pragma unroll
                for (int nt = 0; nt < 4; nt++)
                    mma_tf32(d[mt][nt], ah, bh[nt]);
            }
        }
    }

    float2 bb[4], ssv[4], ttv[4];
    #pragma unroll
    for (int nt = 0; nt < 4; nt++) {
        int c = wc * 32 + nt * 8 + 2 * tig;
        bb[nt] = *(const float2*)(bias + c);
        if (MODE == 1) {
            float2 bv = *(const float2*)(bn_v + c);
            float2 bg = *(const float2*)(bn_g + c);
            float2 bm = *(const float2*)(bn_m + c);
            float2 bbeta = *(const float2*)(bn_b + c);
            float i0 = rsqrtf(fabsf(bv.x) + 1e-5f);
            float i1 = rsqrtf(fabsf(bv.y) + 1e-5f);
            ssv[nt].x = bg.x * i0;
            ssv[nt].y = bg.y * i1;
            ttv[nt].x = bbeta.x - bm.x * ssv[nt].x;
            ttv[nt].y = bbeta.y - bm.y * ssv[nt].y;
        }
    }

    #pragma unroll
    for (int mt = 0; mt < 4; mt++) {
        int r0 = row0 + wr * 64 + mt * 16 + g;
        int r1 = r0 + 8;
        long long b0 = 0, b1 = 0;
        if (OUTK == 2) {
            if (g_idx64) {
                if (r0 < M) b0 = __ldg((const long long*)batch_raw + r0);
                if (r1 < M) b1 = __ldg((const long long*)batch_raw + r1);
            } else {
                if (r0 < M) b0 = __ldg((const int*)batch_raw + r0);
                if (r1 < M) b1 = __ldg((const int*)batch_raw + r1);
            }
        }
        #pragma unroll
        for (int nt = 0; nt < 4; nt++) {
            int c = wc * 32 + nt * 8 + 2 * tig;
            float z0 = d[mt][nt][0] + bb[nt].x;
            float z1 = d[mt][nt][1] + bb[nt].y;
            float z2 = d[mt][nt][2] + bb[nt].x;
            float z3 = d[mt][nt][3] + bb[nt].y;
            if (MODE == 1) {
                z0 = fmaf(z0, ssv[nt].x, ttv[nt].x);
                z1 = fmaf(z1, ssv[nt].y, ttv[nt].y);
                z2 = fmaf(z2, ssv[nt].x, ttv[nt].x);
                z3 = fmaf(z3, ssv[nt].y, ttv[nt].y);
            }
            z0 = fmaxf(z0, 0.0f); z1 = fmaxf(z1, 0.0f);
            z2 = fmaxf(z2, 0.0f); z3 = fmaxf(z3, 0.0f);
            if (OUTK == 2) {
                if (r0 < M && (unsigned long long)b0 < (unsigned long long)GG)
                    red_add_v2(g_pool + (size_t)b0 * HH + c, z0, z1);
                if (r1 < M && (unsigned long long)b1 < (unsigned long long)GG)
                    red_add_v2(g_pool + (size_t)b1 * HH + c, z2, z3);
            } else if (OUTK == 1) {
                if (r0 < M)
                    *(__nv_bfloat162*)(g_hb + (size_t)r0 * HH + c) =
                        __floats2bfloat162_rn(z0, z1);
                if (r1 < M)
                    *(__nv_bfloat162*)(g_hb + (size_t)r1 * HH + c) =
                        __floats2bfloat162_rn(z2, z3);
            } else {
                if (r0 < M)
                    *(float2*)(g_tmp + (size_t)r0 * HH + c) = make_float2(z0, z1);
                if (r1 < M)
                    *(float2*)(g_tmp + (size_t)r1 * HH + c) = make_float2(z2, z3);
            }
        }
    }
}

// ---------------------------------------------------------------------------
__global__ void cnt_kernel(const void* __restrict__ batch_raw, int n) {
    int i = blockIdx.x * blockDim.x + threadIdx.x;
    if (i >= n) return;
    long long b;
    if (g_idx64) b = __ldg((const long long*)batch_raw + i);
    else         b = __ldg((const int*)batch_raw + i);
    if ((unsigned long long)b < (unsigned long long)GG)
        atomicAdd(&g_cnt[b], 1.0f);
}

// ---------------------------------------------------------------------------
__global__ void classifier1_kernel(const float* __restrict__ cls_w1,
                                   const float* __restrict__ cls_b1) {
    __shared__ float sg[GG * HH];
    int tid = threadIdx.x;
    for (int i = tid; i < GG * HH; i += 256) {
        float cnt = g_cnt[i >> 7];
        sg[i] = g_pool[i] / fmaxf(cnt, 1.0f);
    }
    __syncthreads();
    for (int e = tid; e < GG * 64; e += 256) {
        int gi = e >> 6;
        int m  = e & 63;
        float s = cls_b1[m];
        #pragma unroll 8
        for (int k = 0; k < HH; k++)
            s = fmaf(sg[gi * HH + k], cls_w1[k * 64 + m], s);
        g_st[e] = fmaxf(s, 0.0f);
    }
}

__global__ void classifier2_kernel(const float* __restrict__ cls_w2,
                                   const float* __restrict__ cls_b2,
                                   float* __restrict__ out) {
    int g = threadIdx.x;
    if (g < GG) {
        float s = cls_b2[0];
        #pragma unroll 8
        for (int m = 0; m < 64; m++)
            s = fmaf(g_st[g * 64 + m], cls_w2[m], s);
        out[g] = 1.0f / (1.0f + expf(-s));
    }
}

// ---------------------------------------------------------------------------
extern "C" void kernel_launch(void* const* d_in, const int* in_sizes, int n_in,
                              void* d_out, int out_size) {
    const float *x, *edge_attr, *enc_w, *enc_b, *edge_w, *edge_b, *eps;
    const float *mlp_w1, *mlp_b1, *mlp_w2, *mlp_b2;
    const float *bn_gamma, *bn_beta, *bn_mean, *bn_var;
    const float *cls_w1, *cls_b1, *cls_w2, *cls_b2;
    const void *edge_index, *batch;
    int n, E;

    if (in_sizes[1] > 1000) {
        x          = (const float*)d_in[0];
        edge_index = d_in[1];
        edge_attr  = (const float*)d_in[2];
        batch      = d_in[3];
        enc_w      = (const float*)d_in[4];
        enc_b      = (const float*)d_in[5];
        edge_w     = (const float*)d_in[6];
        edge_b     = (const float*)d_in[7];
        eps        = (const float*)d_in[8];
        mlp_w1     = (const float*)d_in[9];
        mlp_b1     = (const float*)d_in[10];
        mlp_w2     = (const float*)d_in[11];
        mlp_b2     = (const float*)d_in[12];
        bn_gamma   = (const float*)d_in[13];
        bn_beta    = (const float*)d_in[14];
        bn_mean    = (const float*)d_in[15];
        bn_var     = (const float*)d_in[16];
        cls_w1     = (const float*)d_in[17];
        cls_b1     = (const float*)d_in[18];
        cls_w2     = (const float*)d_in[19];
        cls_b2     = (const float*)d_in[20];
        n = in_sizes[0];
        E = in_sizes[2];
    } else {
        batch      = d_in[0];
        bn_beta    = (const float*)d_in[1];
        bn_gamma   = (const float*)d_in[2];
        bn_mean    = (const float*)d_in[3];
        bn_var     = (const float*)d_in[4];
        cls_b1     = (const float*)d_in[5];
        cls_b2     = (const float*)d_in[6];
        cls_w1     = (const float*)d_in[7];
        cls_w2     = (const float*)d_in[8];
        edge_attr  = (const float*)d_in[9];
        edge_b     = (const float*)d_in[10];
        edge_index = d_in[11];
        edge_w     = (const float*)d_in[12];
        enc_b      = (const float*)d_in[13];
        enc_w      = (const float*)d_in[14];
        eps        = (const float*)d_in[15];
        mlp_b1     = (const float*)d_in[16];
        mlp_b2     = (const float*)d_in[17];
        mlp_w1     = (const float*)d_in[18];
        mlp_w2     = (const float*)d_in[19];
        x          = (const float*)d_in[20];
        n = in_sizes[20];
        E = in_sizes[9];
    }
    float* out = (float*)d_out;
    if (E > EE_MAX) E = EE_MAX;

    int nblk = (n + 255) / 256;

    // 0) init
    detect_kernel<<<1, 32>>>(edge_index, n);
    zero_misc_kernel<<<nblk, 256>>>(n);
    presplit_kernel<<<(2 * HH * HH + 255) / 256, 256>>>(mlp_w1, mlp_w2);

    // 1) CSR build
    csr_count_kernel<<<(E + 255) / 256, 256>>>(edge_index, E, n);
    blocksum_kernel<<<nblk, 256>>>(n);
    scan_bsum_kernel<<<1, 512>>>(nblk);
    rowptr_kernel<<<nblk, 256>>>(n, E);
    csr_fill_kernel<<<(E + 255) / 256, 256>>>(edge_index, edge_attr, E, n);

    // 2) layers
    int gemm_blocks = (n + 127) / 128;
    int agg_blocks = (n * 32 + 255) / 256;

    aggregate_l0_kernel<<<agg_blocks, 256>>>(x, enc_w, enc_b, edge_w, edge_b,
                                             eps, n);
    gemm128_kernel<0, 0, 0, 0><<<gemm_blocks, 256>>>(
        mlp_b1, nullptr, nullptr, nullptr, nullptr, nullptr, n);
    gemm128_kernel<1, 1, 1, 1><<<gemm_blocks, 256>>>(
        mlp_b2, bn_gamma, bn_beta, bn_mean, bn_var, nullptr, n);

    aggregate_kernel<<<agg_blocks, 256>>>(edge_w, edge_b, eps + 1, n);
    gemm128_kernel<0, 0, 0, 2><<<gemm_blocks, 256>>>(
        mlp_b1 + HH, nullptr, nullptr, nullptr, nullptr, nullptr, n);
    gemm128_kernel<1, 2, 1, 3><<<gemm_blocks, 256>>>(
        mlp_b2 + HH, bn_gamma + HH, bn_beta + HH, bn_mean + HH, bn_var + HH,
        batch, n);

    // 3) counts + classifier
    cnt_kernel<<<nblk, 256>>>(batch, n);
    classifier1_kernel<<<1, 256>>>(cls_w1, cls_b1);
    classifier2_kernel<<<1, 64>>>(cls_w2, cls_b2, out);
}

// round 11
// speedup vs baseline: 1.4139x; 1.0826x over previous
#include <cuda_runtime.h>
#include <cuda_bf16.h>
#include <math.h>

// Fixed problem shape
#define HH 128
#define GG 64
#define NN_MAX 100000
#define EE_MAX 1600000

typedef unsigned long long u64;
typedef unsigned int u32;

// Scratch: __device__ globals, referenced ONLY inside device code.
__device__ __nv_bfloat16 g_hb[NN_MAX * HH];     // node features (bf16)
__device__ __nv_bfloat16 g_aggrb[NN_MAX * HH];  // aggregate output (bf16)
__device__ __nv_bfloat16 g_tmpb[NN_MAX * HH];   // MLP hidden (bf16)
__device__ float g_pool[GG * HH];
__device__ float g_cnt[GG];
__device__ float g_st[GG * 64];
__device__ int   g_idx64;           // 1 if edge_index/batch are int64

// Pre-converted bf16 weights, TRANSPOSED [c][k]: mats 0=W1L0,1=W2L0,2=W1L1,3=W2L1
__device__ __nv_bfloat16 g_Wt[4 * HH * HH];

// CSR scratch (built once per call; graph shared by both layers)
__device__ int   g_deg[NN_MAX];
__device__ int   g_rowptr[NN_MAX + 1];
__device__ int   g_cursor[NN_MAX];
__device__ int   g_bsum[512];
__device__ int   g_boff[512];
__device__ int   g_esrc[EE_MAX];
__device__ float g_eea[EE_MAX];

__device__ __forceinline__ void red_add_v2(float* p, float a, float b) {
    asm volatile("red.global.add.v2.f32 [%0], {%1,%2};"
                 :: "l"(p), "f"(a), "f"(b) : "memory");
}

// bf16 mma m16n8k16 (row.col): A 4 regs (8 bf16), B 2 regs (4 bf16), D 4 f32
__device__ __forceinline__ void mma_bf16(float d[4], const u32 a[4],
                                         const u32 b[2]) {
    asm("mma.sync.aligned.m16n8k16.row.col.f32.bf16.bf16.f32 "
        "{%0,%1,%2,%3}, {%4,%5,%6,%7}, {%8,%9}, {%0,%1,%2,%3};"
        : "+f"(d[0]), "+f"(d[1]), "+f"(d[2]), "+f"(d[3])
        : "r"(a[0]), "r"(a[1]), "r"(a[2]), "r"(a[3]), "r"(b[0]), "r"(b[1]));
}

__device__ __forceinline__ uint2 pack_bf16x4(float4 v) {
    __nv_bfloat162 p0 = __floats2bfloat162_rn(v.x, v.y);
    __nv_bfloat162 p1 = __floats2bfloat162_rn(v.z, v.w);
    uint2 o;
    o.x = *reinterpret_cast<u32*>(&p0);
    o.y = *reinterpret_cast<u32*>(&p1);
    return o;
}

__device__ __forceinline__ float4 ldhb4(const __nv_bfloat16* p) {
    uint2 rv = *(const uint2*)p;
    __nv_bfloat162 b0 = *reinterpret_cast<__nv_bfloat162*>(&rv.x);
    __nv_bfloat162 b1 = *reinterpret_cast<__nv_bfloat162*>(&rv.y);
    float2 f0 = __bfloat1622float2(b0);
    float2 f1 = __bfloat1622float2(b1);
    return make_float4(f0.x, f0.y, f1.x, f1.y);
}

// ---------------------------------------------------------------------------
__global__ void detect_kernel(const void* ei_raw, int n) {
    if (threadIdx.x == 0 && blockIdx.x == 0) {
        const long long* p = (const long long*)ei_raw;
        int ok = 1;
        for (int i = 0; i < 16; i++) {
            long long v = p[i];
            if (v < 0 || v >= (long long)n) ok = 0;
        }
        g_idx64 = ok;
    }
}

__global__ void zero_misc_kernel(int n) {
    int i = blockIdx.x * blockDim.x + threadIdx.x;
    if (i < n) g_deg[i] = 0;
    if (i < GG * HH) g_pool[i] = 0.0f;
    if (i < GG) g_cnt[i] = 0.0f;
}

// Pre-convert W1/W2 (both layers) to bf16, transposed [c][k].
__global__ void presplit_kernel(const float* __restrict__ w1,
                                const float* __restrict__ w2) {
    int i = blockIdx.x * blockDim.x + threadIdx.x;   // 0 .. 2*HH*HH-1
    if (i >= 2 * HH * HH) return;
    int l = i >> 14;
    int off = i & 16383;
    int k = off >> 7;
    int c = off & 127;
    g_Wt[(l * 2 + 0) * 16384 + c * HH + k] = __float2bfloat16(__ldg(w1 + i));
    g_Wt[(l * 2 + 1) * 16384 + c * HH + k] = __float2bfloat16(__ldg(w2 + i));
}

// ============================ CSR build (once) =============================
__global__ void csr_count_kernel(const void* __restrict__ ei_raw, int E, int n) {
    int e = blockIdx.x * blockDim.x + threadIdx.x;
    if (e >= E) return;
    long long dst;
    if (g_idx64) dst = __ldg((const long long*)ei_raw + E + e);
    else         dst = __ldg((const int*)ei_raw + E + e);
    if ((unsigned long long)dst >= (unsigned long long)n) return;
    atomicAdd(&g_deg[(int)dst], 1);
}

__global__ void blocksum_kernel(int n) {
    __shared__ int s[256];
    int t = threadIdx.x;
    int i = blockIdx.x * 256 + t;
    s[t] = (i < n) ? g_deg[i] : 0;
    __syncthreads();
    for (int d = 128; d > 0; d >>= 1) {
        if (t < d) s[t] += s[t + d];
        __syncthreads();
    }
    if (t == 0) g_bsum[blockIdx.x] = s[0];
}

__global__ void scan_bsum_kernel(int nb) {
    __shared__ int s[512];
    int t = threadIdx.x;
    int v0 = (t < nb) ? g_bsum[t] : 0;
    s[t] = v0;
    __syncthreads();
    for (int d = 1; d < 512; d <<= 1) {
        int v = (t >= d) ? s[t - d] : 0;
        __syncthreads();
        s[t] += v;
        __syncthreads();
    }
    g_boff[t] = s[t] - v0;
}

__global__ void rowptr_kernel(int n, int E) {
    __shared__ int s[256];
    int t = threadIdx.x;
    int i = blockIdx.x * 256 + t;
    int d = (i < n) ? g_deg[i] : 0;
    s[t] = d;
    __syncthreads();
    for (int dd = 1; dd < 256; dd <<= 1) {
        int v = (t >= dd) ? s[t - dd] : 0;
        __syncthreads();
        s[t] += v;
        __syncthreads();
    }
    int excl = s[t] - d + g_boff[blockIdx.x];
    if (i < n) {
        g_rowptr[i] = excl;
        g_cursor[i] = excl;
        if (i == n - 1) g_rowptr[n] = E;
    }
}

__global__ void csr_fill_kernel(const void* __restrict__ ei_raw,
                                const float* __restrict__ edge_attr,
                                int E, int n) {
    int e = blockIdx.x * blockDim.x + threadIdx.x;
    if (e >= E) return;
    long long src, dst;
    if (g_idx64) {
        const long long* ei = (const long long*)ei_raw;
        src = __ldg(ei + e);
        dst = __ldg(ei + E + e);
    } else {
        const int* ei = (const int*)ei_raw;
        src = __ldg(ei + e);
        dst = __ldg(ei + E + e);
    }
    if ((unsigned long long)src >= (unsigned long long)n ||
        (unsigned long long)dst >= (unsigned long long)n) return;
    int pos = atomicAdd(&g_cursor[(int)dst], 1);
    g_esrc[pos] = (int)src;
    g_eea[pos]  = __ldg(edge_attr + e);
}

// ==================== aggregate layer 0 (rank-1 h) ==========================
__global__ void aggregate_l0_kernel(const float* __restrict__ x,
                                    const float* __restrict__ enc_w,
                                    const float* __restrict__ enc_b,
                                    const float* __restrict__ edge_w,
                                    const float* __restrict__ edge_b,
                                    const float* __restrict__ eps0, int n) {
    int gt = blockIdx.x * blockDim.x + threadIdx.x;
    int i = gt >> 5;
    if (i >= n) return;
    int lane = gt & 31;
    int c = lane * 4;
    float4 cw = *(const float4*)(enc_w + c);
    float4 cb = *(const float4*)(enc_b + c);
    float4 ew = *(const float4*)(edge_w + c);
    float4 eb = *(const float4*)(edge_b + c);
    float4 mb;
    mb.x = cb.x + eb.x; mb.y = cb.y + eb.y;
    mb.z = cb.z + eb.z; mb.w = cb.w + eb.w;
    float s = 1.0f + __ldg(eps0);
    float xi = __ldg(x + i);
    float4 acc;
    acc.x = s * fmaf(xi, cw.x, cb.x);
    acc.y = s * fmaf(xi, cw.y, cb.y);
    acc.z = s * fmaf(xi, cw.z, cb.z);
    acc.w = s * fmaf(xi, cw.w, cb.w);

    int k0 = __ldg(&g_rowptr[i]);
    int k1 = __ldg(&g_rowptr[i + 1]);
    for (int k = k0; k < k1; k++) {
        float xs = __ldg(x + __ldg(&g_esrc[k]));
        float ea = __ldg(&g_eea[k]);
        acc.x += fmaxf(fmaf(xs, cw.x, fmaf(ea, ew.x, mb.x)), 0.0f);
        acc.y += fmaxf(fmaf(xs, cw.y, fmaf(ea, ew.y, mb.y)), 0.0f);
        acc.z += fmaxf(fmaf(xs, cw.z, fmaf(ea, ew.z, mb.z)), 0.0f);
        acc.w += fmaxf(fmaf(xs, cw.w, fmaf(ea, ew.w, mb.w)), 0.0f);
    }
    *(uint2*)(g_aggrb + (size_t)i * HH + c) = pack_bf16x4(acc);
}

// ==================== aggregate layer 1 (bf16 h gather) =====================
__global__ void aggregate_kernel(const float* __restrict__ edge_w,
                                 const float* __restrict__ edge_b,
                                 const float* __restrict__ eps_l, int n) {
    int gt = blockIdx.x * blockDim.x + threadIdx.x;
    int i = gt >> 5;
    if (i >= n) return;
    int lane = gt & 31;
    int c = lane * 4;
    float4 ew = *(const float4*)(edge_w + c);
    float4 eb = *(const float4*)(edge_b + c);
    float s = 1.0f + __ldg(eps_l);

    float4 hv = ldhb4(g_hb + (size_t)i * HH + c);
    float4 acc;
    acc.x = hv.x * s; acc.y = hv.y * s; acc.z = hv.z * s; acc.w = hv.w * s;

    int k0 = __ldg(&g_rowptr[i]);
    int k1 = __ldg(&g_rowptr[i + 1]);
    int k = k0;
    for (; k + 8 <= k1; k += 8) {
        int si[8]; float ai[8]; float4 vv[8];
        #pragma unroll
        for (int u = 0; u < 8; u++) si[u] = __ldg(&g_esrc[k + u]);
        #pragma unroll
        for (int u = 0; u < 8; u++) ai[u] = __ldg(&g_eea[k + u]);
        #pragma unroll
        for (int u = 0; u < 8; u++)
            vv[u] = ldhb4(g_hb + (size_t)si[u] * HH + c);
        #pragma unroll
        for (int u = 0; u < 8; u++) {
            acc.x += fmaxf(vv[u].x + fmaf(ai[u], ew.x, eb.x), 0.0f);
            acc.y += fmaxf(vv[u].y + fmaf(ai[u], ew.y, eb.y), 0.0f);
            acc.z += fmaxf(vv[u].z + fmaf(ai[u], ew.z, eb.z), 0.0f);
            acc.w += fmaxf(vv[u].w + fmaf(ai[u], ew.w, eb.w), 0.0f);
        }
    }
    for (; k < k1; k++) {
        int src = __ldg(&g_esrc[k]);
        float ea = __ldg(&g_eea[k]);
        float4 sv = ldhb4(g_hb + (size_t)src * HH + c);
        acc.x += fmaxf(sv.x + fmaf(ea, ew.x, eb.x), 0.0f);
        acc.y += fmaxf(sv.y + fmaf(ea, ew.y, eb.y), 0.0f);
        acc.z += fmaxf(sv.z + fmaf(ea, ew.z, eb.z), 0.0f);
        acc.w += fmaxf(sv.w + fmaf(ea, ew.w, eb.w), 0.0f);
    }
    *(uint2*)(g_aggrb + (size_t)i * HH + c) = pack_bf16x4(acc);
}

// ---------------------------------------------------------------------------
// bf16 tensor-core GEMM: C = act(A @ W + bias), A bf16, W bf16 transposed.
// mma.m16n8k16, 8 warps (2x4), warp tile 64x32, BK=16 (one mma k-step/chunk).
// smem row-major, stride 24 halves -> conflict-free fragment loads.
// MODE 0: bias+relu. MODE 1: bias+BN+relu.
// OUTK 0: bf16 -> g_tmpb. OUTK 1: bf16 -> g_hb. OUTK 2: pool reduction.
// SRCB 0: A = g_aggrb, 1: A = g_tmpb. WIDX selects weight matrix.
#define SWH 24    // smem stride in halves (48 B)
template <int MODE, int OUTK, int SRCB, int WIDX>
__global__ void __launch_bounds__(256, 2)
gemm128_kernel(const float* __restrict__ bias,
               const float* __restrict__ bn_g,
               const float* __restrict__ bn_b,
               const float* __restrict__ bn_m,
               const float* __restrict__ bn_v,
               const void* __restrict__ batch_raw,
               int M) {
    const __nv_bfloat16* A = SRCB == 0 ? g_aggrb : g_tmpb;
    const __nv_bfloat16* Wt = g_Wt + WIDX * (HH * HH);

    __shared__ __nv_bfloat16 sA[128 * SWH];   // [r][k]  6.1 KB
    __shared__ __nv_bfloat16 sW[128 * SWH];   // [c][k]  6.1 KB

    int tid = threadIdx.x;
    int lane = tid & 31;
    int wid = tid >> 5;
    int g = lane >> 2;
    int tig = lane & 3;
    int wr = wid >> 2;
    int wc = wid & 3;
    int row0 = blockIdx.x * 128;

    float d[4][4][4];
    #pragma unroll
    for (int i = 0; i < 4; i++)
        #pragma unroll
        for (int j = 0; j < 4; j++)
            #pragma unroll
            for (int r = 0; r < 4; r++) d[i][j][r] = 0.0f;

    int fr = tid >> 1;            // fill row/col (0..127)
    int fo = (tid & 1) * 8;       // half offset within chunk (0 or 8)

    for (int k0 = 0; k0 < HH; k0 += 16) {
        __syncthreads();
        // W chunk: [128 c][16 k] bf16 — pure uint4 copy
        {
            uint4 v = *(const uint4*)(Wt + (size_t)fr * HH + k0 + fo);
            *(uint2*)(sW + fr * SWH + fo)     = make_uint2(v.x, v.y);
            *(uint2*)(sW + fr * SWH + fo + 4) = make_uint2(v.z, v.w);
        }
        // A chunk: [128 r][16 k] bf16 — uint4 copy with bound guard
        {
            int grow = row0 + fr;
            uint4 v = (grow < M)
                ? *(const uint4*)(A + (size_t)grow * HH + k0 + fo)
                : make_uint4(0u, 0u, 0u, 0u);
            *(uint2*)(sA + fr * SWH + fo)     = make_uint2(v.x, v.y);
            *(uint2*)(sA + fr * SWH + fo + 4) = make_uint2(v.z, v.w);
        }
        __syncthreads();

        // one m16n8k16 k-step per chunk
        u32 bf[4][2];
        #pragma unroll
        for (int nt = 0; nt < 4; nt++) {
            int cc = wc * 32 + nt * 8 + g;
            bf[nt][0] = *(const u32*)(sW + cc * SWH + 2 * tig);
            bf[nt][1] = *(const u32*)(sW + cc * SWH + 2 * tig + 8);
        }
        #pragma unroll
        for (int mt = 0; mt < 4; mt++) {
            int rr = wr * 64 + mt * 16 + g;
            u32 a[4];
            a[0] = *(const u32*)(sA + rr * SWH + 2 * tig);
            a[1] = *(const u32*)(sA + (rr + 8) * SWH + 2 * tig);
            a[2] = *(const u32*)(sA + rr * SWH + 2 * tig + 8);
            a[3] = *(const u32*)(sA + (rr + 8) * SWH + 2 * tig + 8);
            #pragma unroll
            for (int nt = 0; nt < 4; nt++)
                mma_bf16(d[mt][nt], a, bf[nt]);
        }
    }

    float2 bb[4], ssv[4], ttv[4];
    #pragma unroll
    for (int nt = 0; nt < 4; nt++) {
        int c = wc * 32 + nt * 8 + 2 * tig;
        bb[nt] = *(const float2*)(bias + c);
        if (MODE == 1) {
            float2 bv = *(const float2*)(bn_v + c);
            float2 bg = *(const float2*)(bn_g + c);
            float2 bm = *(const float2*)(bn_m + c);
            float2 bbeta = *(const float2*)(bn_b + c);
            float i0 = rsqrtf(fabsf(bv.x) + 1e-5f);
            float i1 = rsqrtf(fabsf(bv.y) + 1e-5f);
            ssv[nt].x = bg.x * i0;
            ssv[nt].y = bg.y * i1;
            ttv[nt].x = bbeta.x - bm.x * ssv[nt].x;
            ttv[nt].y = bbeta.y - bm.y * ssv[nt].y;
        }
    }

    #pragma unroll
    for (int mt = 0; mt < 4; mt++) {
        int r0 = row0 + wr * 64 + mt * 16 + g;
        int r1 = r0 + 8;
        long long b0 = 0, b1 = 0;
        if (OUTK == 2) {
            if (g_idx64) {
                if (r0 < M) b0 = __ldg((const long long*)batch_raw + r0);
                if (r1 < M) b1 = __ldg((const long long*)batch_raw + r1);
            } else {
                if (r0 < M) b0 = __ldg((const int*)batch_raw + r0);
                if (r1 < M) b1 = __ldg((const int*)batch_raw + r1);
            }
        }
        #pragma unroll
        for (int nt = 0; nt < 4; nt++) {
            int c = wc * 32 + nt * 8 + 2 * tig;
            float z0 = d[mt][nt][0] + bb[nt].x;
            float z1 = d[mt][nt][1] + bb[nt].y;
            float z2 = d[mt][nt][2] + bb[nt].x;
            float z3 = d[mt][nt][3] + bb[nt].y;
            if (MODE == 1) {
                z0 = fmaf(z0, ssv[nt].x, ttv[nt].x);
                z1 = fmaf(z1, ssv[nt].y, ttv[nt].y);
                z2 = fmaf(z2, ssv[nt].x, ttv[nt].x);
                z3 = fmaf(z3, ssv[nt].y, ttv[nt].y);
            }
            z0 = fmaxf(z0, 0.0f); z1 = fmaxf(z1, 0.0f);
            z2 = fmaxf(z2, 0.0f); z3 = fmaxf(z3, 0.0f);
            if (OUTK == 2) {
                if (r0 < M && (unsigned long long)b0 < (unsigned long long)GG)
                    red_add_v2(g_pool + (size_t)b0 * HH + c, z0, z1);
                if (r1 < M && (unsigned long long)b1 < (unsigned long long)GG)
                    red_add_v2(g_pool + (size_t)b1 * HH + c, z2, z3);
            } else {
                __nv_bfloat16* O = (OUTK == 1) ? g_hb : g_tmpb;
                if (r0 < M)
                    *(__nv_bfloat162*)(O + (size_t)r0 * HH + c) =
                        __floats2bfloat162_rn(z0, z1);
                if (r1 < M)
                    *(__nv_bfloat162*)(O + (size_t)r1 * HH + c) =
                        __floats2bfloat162_rn(z2, z3);
            }
        }
    }
}

// ---------------------------------------------------------------------------
__global__ void cnt_kernel(const void* __restrict__ batch_raw, int n) {
    int i = blockIdx.x * blockDim.x + threadIdx.x;
    if (i >= n) return;
    long long b;
    if (g_idx64) b = __ldg((const long long*)batch_raw + i);
    else         b = __ldg((const int*)batch_raw + i);
    if ((unsigned long long)b < (unsigned long long)GG)
        atomicAdd(&g_cnt[b], 1.0f);
}

// ---------------------------------------------------------------------------
__global__ void classifier1_kernel(const float* __restrict__ cls_w1,
                                   const float* __restrict__ cls_b1) {
    __shared__ float sg[GG * HH];
    int tid = threadIdx.x;
    for (int i = tid; i < GG * HH; i += 256) {
        float cnt = g_cnt[i >> 7];
        sg[i] = g_pool[i] / fmaxf(cnt, 1.0f);
    }
    __syncthreads();
    for (int e = tid; e < GG * 64; e += 256) {
        int gi = e >> 6;
        int m  = e & 63;
        float s = cls_b1[m];
        #pragma unroll 8
        for (int k = 0; k < HH; k++)
            s = fmaf(sg[gi * HH + k], cls_w1[k * 64 + m], s);
        g_st[e] = fmaxf(s, 0.0f);
    }
}

__global__ void classifier2_kernel(const float* __restrict__ cls_w2,
                                   const float* __restrict__ cls_b2,
                                   float* __restrict__ out) {
    int g = threadIdx.x;
    if (g < GG) {
        float s = cls_b2[0];
        #pragma unroll 8
        for (int m = 0; m < 64; m++)
            s = fmaf(g_st[g * 64 + m], cls_w2[m], s);
        out[g] = 1.0f / (1.0f + expf(-s));
    }
}

// ---------------------------------------------------------------------------
extern "C" void kernel_launch(void* const* d_in, const int* in_sizes, int n_in,
                              void* d_out, int out_size) {
    const float *x, *edge_attr, *enc_w, *enc_b, *edge_w, *edge_b, *eps;
    const float *mlp_w1, *mlp_b1, *mlp_w2, *mlp_b2;
    const float *bn_gamma, *bn_beta, *bn_mean, *bn_var;
    const float *cls_w1, *cls_b1, *cls_w2, *cls_b2;
    const void *edge_index, *batch;
    int n, E;

    if (in_sizes[1] > 1000) {
        x          = (const float*)d_in[0];
        edge_index = d_in[1];
        edge_attr  = (const float*)d_in[2];
        batch      = d_in[3];
        enc_w      = (const float*)d_in[4];
        enc_b      = (const float*)d_in[5];
        edge_w     = (const float*)d_in[6];
        edge_b     = (const float*)d_in[7];
        eps        = (const float*)d_in[8];
        mlp_w1     = (const float*)d_in[9];
        mlp_b1     = (const float*)d_in[10];
        mlp_w2     = (const float*)d_in[11];
        mlp_b2     = (const float*)d_in[12];
        bn_gamma   = (const float*)d_in[13];
        bn_beta    = (const float*)d_in[14];
        bn_mean    = (const float*)d_in[15];
        bn_var     = (const float*)d_in[16];
        cls_w1     = (const float*)d_in[17];
        cls_b1     = (const float*)d_in[18];
        cls_w2     = (const float*)d_in[19];
        cls_b2     = (const float*)d_in[20];
        n = in_sizes[0];
        E = in_sizes[2];
    } else {
        batch      = d_in[0];
        bn_beta    = (const float*)d_in[1];
        bn_gamma   = (const float*)d_in[2];
        bn_mean    = (const float*)d_in[3];
        bn_var     = (const float*)d_in[4];
        cls_b1     = (const float*)d_in[5];
        cls_b2     = (const float*)d_in[6];
        cls_w1     = (const float*)d_in[7];
        cls_w2     = (const float*)d_in[8];
        edge_attr  = (const float*)d_in[9];
        edge_b     = (const float*)d_in[10];
        edge_index = d_in[11];
        edge_w     = (const float*)d_in[12];
        enc_b      = (const float*)d_in[13];
        enc_w      = (const float*)d_in[14];
        eps        = (const float*)d_in[15];
        mlp_b1     = (const float*)d_in[16];
        mlp_b2     = (const float*)d_in[17];
        mlp_w1     = (const float*)d_in[18];
        mlp_w2     = (const float*)d_in[19];
        x          = (const float*)d_in[20];
        n = in_sizes[20];
        E = in_sizes[9];
    }
    float* out = (float*)d_out;
    if (E > EE_MAX) E = EE_MAX;

    int nblk = (n + 255) / 256;

    // 0) init
    detect_kernel<<<1, 32>>>(edge_index, n);
    zero_misc_kernel<<<nblk, 256>>>(n);
    presplit_kernel<<<(2 * HH * HH + 255) / 256, 256>>>(mlp_w1, mlp_w2);

    // 1) CSR build
    csr_count_kernel<<<(E + 255) / 256, 256>>>(edge_index, E, n);
    blocksum_kernel<<<nblk, 256>>>(n);
    scan_bsum_kernel<<<1, 512>>>(nblk);
    rowptr_kernel<<<nblk, 256>>>(n, E);
    csr_fill_kernel<<<(E + 255) / 256, 256>>>(edge_index, edge_attr, E, n);

    // 2) layers
    int gemm_blocks = (n + 127) / 128;
    int agg_blocks = (n * 32 + 255) / 256;

    aggregate_l0_kernel<<<agg_blocks, 256>>>(x, enc_w, enc_b, edge_w, edge_b,
                                             eps, n);
    gemm128_kernel<0, 0, 0, 0><<<gemm_blocks, 256>>>(
        mlp_b1, nullptr, nullptr, nullptr, nullptr, nullptr, n);
    gemm128_kernel<1, 1, 1, 1><<<gemm_blocks, 256>>>(
        mlp_b2, bn_gamma, bn_beta, bn_mean, bn_var, nullptr, n);

    aggregate_kernel<<<agg_blocks, 256>>>(edge_w, edge_b, eps + 1, n);
    gemm128_kernel<0, 0, 0, 2><<<gemm_blocks, 256>>>(
        mlp_b1 + HH, nullptr, nullptr, nullptr, nullptr, nullptr, n);
    gemm128_kernel<1, 2, 1, 3><<<gemm_blocks, 256>>>(
        mlp_b2 + HH, bn_gamma + HH, bn_beta + HH, bn_mean + HH, bn_var + HH,
        batch, n);

    // 3) counts + classifier
    cnt_kernel<<<nblk, 256>>>(batch, n);
    classifier1_kernel<<<1, 256>>>(cls_w1, cls_b1);
    classifier2_kernel<<<1, 64>>>(cls_w2, cls_b2, out);
}

// round 12
// speedup vs baseline: 1.4784x; 1.0456x over previous
#include <cuda_runtime.h>
#include <cuda_bf16.h>
#include <math.h>

// Fixed problem shape
#define HH 128
#define GG 64
#define NN_MAX 100000
#define EE_MAX 1600000

typedef unsigned long long u64;
typedef unsigned int u32;

// Scratch: __device__ globals, referenced ONLY inside device code.
__device__ __nv_bfloat16 g_hb[NN_MAX * HH];     // node features (bf16)
__device__ __nv_bfloat16 g_aggrb[NN_MAX * HH];  // aggregate output (bf16)
__device__ float g_pool[GG * HH];
__device__ float g_cnt[GG];
__device__ float g_st[GG * 64];
__device__ int   g_idx64;           // 1 if edge_index/batch are int64

// Pre-converted bf16 weights, TRANSPOSED [c][k]: mats 0=W1L0,1=W2L0,2=W1L1,3=W2L1
__device__ __nv_bfloat16 g_Wt[4 * HH * HH];

// CSR scratch (built once per call; graph shared by both layers)
__device__ int   g_deg[NN_MAX];
__device__ int   g_rowptr[NN_MAX + 1];
__device__ int   g_cursor[NN_MAX];
__device__ int   g_bsum[512];
__device__ int   g_boff[512];
__device__ int   g_esrc[EE_MAX];
__device__ float g_eea[EE_MAX];

__device__ __forceinline__ void red_add_v2(float* p, float a, float b) {
    asm volatile("red.global.add.v2.f32 [%0], {%1,%2};"
                 :: "l"(p), "f"(a), "f"(b) : "memory");
}

// bf16 mma m16n8k16 (row.col): A 4 regs (8 bf16), B 2 regs (4 bf16), D 4 f32
__device__ __forceinline__ void mma_bf16(float d[4], const u32 a[4],
                                         const u32 b[2]) {
    asm("mma.sync.aligned.m16n8k16.row.col.f32.bf16.bf16.f32 "
        "{%0,%1,%2,%3}, {%4,%5,%6,%7}, {%8,%9}, {%0,%1,%2,%3};"
        : "+f"(d[0]), "+f"(d[1]), "+f"(d[2]), "+f"(d[3])
        : "r"(a[0]), "r"(a[1]), "r"(a[2]), "r"(a[3]), "r"(b[0]), "r"(b[1]));
}

__device__ __forceinline__ uint2 pack_bf16x4(float4 v) {
    __nv_bfloat162 p0 = __floats2bfloat162_rn(v.x, v.y);
    __nv_bfloat162 p1 = __floats2bfloat162_rn(v.z, v.w);
    uint2 o;
    o.x = *reinterpret_cast<u32*>(&p0);
    o.y = *reinterpret_cast<u32*>(&p1);
    return o;
}

__device__ __forceinline__ float4 ldhb4(const __nv_bfloat16* p) {
    uint2 rv = *(const uint2*)p;
    __nv_bfloat162 b0 = *reinterpret_cast<__nv_bfloat162*>(&rv.x);
    __nv_bfloat162 b1 = *reinterpret_cast<__nv_bfloat162*>(&rv.y);
    float2 f0 = __bfloat1622float2(b0);
    float2 f1 = __bfloat1622float2(b1);
    return make_float4(f0.x, f0.y, f1.x, f1.y);
}

// ---------------------------------------------------------------------------
__global__ void detect_kernel(const void* ei_raw, int n) {
    if (threadIdx.x == 0 && blockIdx.x == 0) {
        const long long* p = (const long long*)ei_raw;
        int ok = 1;
        for (int i = 0; i < 16; i++) {
            long long v = p[i];
            if (v < 0 || v >= (long long)n) ok = 0;
        }
        g_idx64 = ok;
    }
}

__global__ void zero_misc_kernel(int n) {
    int i = blockIdx.x * blockDim.x + threadIdx.x;
    if (i < n) g_deg[i] = 0;
    if (i < GG * HH) g_pool[i] = 0.0f;
    if (i < GG) g_cnt[i] = 0.0f;
}

// Pre-convert W1/W2 (both layers) to bf16, transposed [c][k].
__global__ void presplit_kernel(const float* __restrict__ w1,
                                const float* __restrict__ w2) {
    int i = blockIdx.x * blockDim.x + threadIdx.x;   // 0 .. 2*HH*HH-1
    if (i >= 2 * HH * HH) return;
    int l = i >> 14;
    int off = i & 16383;
    int k = off >> 7;
    int c = off & 127;
    g_Wt[(l * 2 + 0) * 16384 + c * HH + k] = __float2bfloat16(__ldg(w1 + i));
    g_Wt[(l * 2 + 1) * 16384 + c * HH + k] = __float2bfloat16(__ldg(w2 + i));
}

// ============================ CSR build (once) =============================
__global__ void csr_count_kernel(const void* __restrict__ ei_raw, int E, int n) {
    int e = blockIdx.x * blockDim.x + threadIdx.x;
    if (e >= E) return;
    long long dst;
    if (g_idx64) dst = __ldg((const long long*)ei_raw + E + e);
    else         dst = __ldg((const int*)ei_raw + E + e);
    if ((unsigned long long)dst >= (unsigned long long)n) return;
    atomicAdd(&g_deg[(int)dst], 1);
}

__global__ void blocksum_kernel(int n) {
    __shared__ int s[256];
    int t = threadIdx.x;
    int i = blockIdx.x * 256 + t;
    s[t] = (i < n) ? g_deg[i] : 0;
    __syncthreads();
    for (int d = 128; d > 0; d >>= 1) {
        if (t < d) s[t] += s[t + d];
        __syncthreads();
    }
    if (t == 0) g_bsum[blockIdx.x] = s[0];
}

__global__ void scan_bsum_kernel(int nb) {
    __shared__ int s[512];
    int t = threadIdx.x;
    int v0 = (t < nb) ? g_bsum[t] : 0;
    s[t] = v0;
    __syncthreads();
    for (int d = 1; d < 512; d <<= 1) {
        int v = (t >= d) ? s[t - d] : 0;
        __syncthreads();
        s[t] += v;
        __syncthreads();
    }
    g_boff[t] = s[t] - v0;
}

__global__ void rowptr_kernel(int n, int E) {
    __shared__ int s[256];
    int t = threadIdx.x;
    int i = blockIdx.x * 256 + t;
    int d = (i < n) ? g_deg[i] : 0;
    s[t] = d;
    __syncthreads();
    for (int dd = 1; dd < 256; dd <<= 1) {
        int v = (t >= dd) ? s[t - dd] : 0;
        __syncthreads();
        s[t] += v;
        __syncthreads();
    }
    int excl = s[t] - d + g_boff[blockIdx.x];
    if (i < n) {
        g_rowptr[i] = excl;
        g_cursor[i] = excl;
        if (i == n - 1) g_rowptr[n] = E;
    }
}

__global__ void csr_fill_kernel(const void* __restrict__ ei_raw,
                                const float* __restrict__ edge_attr,
                                int E, int n) {
    int e = blockIdx.x * blockDim.x + threadIdx.x;
    if (e >= E) return;
    long long src, dst;
    if (g_idx64) {
        const long long* ei = (const long long*)ei_raw;
        src = __ldg(ei + e);
        dst = __ldg(ei + E + e);
    } else {
        const int* ei = (const int*)ei_raw;
        src = __ldg(ei + e);
        dst = __ldg(ei + E + e);
    }
    if ((unsigned long long)src >= (unsigned long long)n ||
        (unsigned long long)dst >= (unsigned long long)n) return;
    int pos = atomicAdd(&g_cursor[(int)dst], 1);
    g_esrc[pos] = (int)src;
    g_eea[pos]  = __ldg(edge_attr + e);
}

// ==================== aggregate layer 0 (rank-1 h) ==========================
__global__ void aggregate_l0_kernel(const float* __restrict__ x,
                                    const float* __restrict__ enc_w,
                                    const float* __restrict__ enc_b,
                                    const float* __restrict__ edge_w,
                                    const float* __restrict__ edge_b,
                                    const float* __restrict__ eps0, int n) {
    int gt = blockIdx.x * blockDim.x + threadIdx.x;
    int i = gt >> 5;
    if (i >= n) return;
    int lane = gt & 31;
    int c = lane * 4;
    float4 cw = *(const float4*)(enc_w + c);
    float4 cb = *(const float4*)(enc_b + c);
    float4 ew = *(const float4*)(edge_w + c);
    float4 eb = *(const float4*)(edge_b + c);
    float4 mb;
    mb.x = cb.x + eb.x; mb.y = cb.y + eb.y;
    mb.z = cb.z + eb.z; mb.w = cb.w + eb.w;
    float s = 1.0f + __ldg(eps0);
    float xi = __ldg(x + i);
    float4 acc;
    acc.x = s * fmaf(xi, cw.x, cb.x);
    acc.y = s * fmaf(xi, cw.y, cb.y);
    acc.z = s * fmaf(xi, cw.z, cb.z);
    acc.w = s * fmaf(xi, cw.w, cb.w);

    int k0 = __ldg(&g_rowptr[i]);
    int k1 = __ldg(&g_rowptr[i + 1]);
    for (int k = k0; k < k1; k++) {
        float xs = __ldg(x + __ldg(&g_esrc[k]));
        float ea = __ldg(&g_eea[k]);
        acc.x += fmaxf(fmaf(xs, cw.x, fmaf(ea, ew.x, mb.x)), 0.0f);
        acc.y += fmaxf(fmaf(xs, cw.y, fmaf(ea, ew.y, mb.y)), 0.0f);
        acc.z += fmaxf(fmaf(xs, cw.z, fmaf(ea, ew.z, mb.z)), 0.0f);
        acc.w += fmaxf(fmaf(xs, cw.w, fmaf(ea, ew.w, mb.w)), 0.0f);
    }
    *(uint2*)(g_aggrb + (size_t)i * HH + c) = pack_bf16x4(acc);
}

// ==================== aggregate layer 1 (bf16 h gather) =====================
__global__ void aggregate_kernel(const float* __restrict__ edge_w,
                                 const float* __restrict__ edge_b,
                                 const float* __restrict__ eps_l, int n) {
    int gt = blockIdx.x * blockDim.x + threadIdx.x;
    int i = gt >> 5;
    if (i >= n) return;
    int lane = gt & 31;
    int c = lane * 4;
    float4 ew = *(const float4*)(edge_w + c);
    float4 eb = *(const float4*)(edge_b + c);
    float s = 1.0f + __ldg(eps_l);

    float4 hv = ldhb4(g_hb + (size_t)i * HH + c);
    float4 acc;
    acc.x = hv.x * s; acc.y = hv.y * s; acc.z = hv.z * s; acc.w = hv.w * s;

    int k0 = __ldg(&g_rowptr[i]);
    int k1 = __ldg(&g_rowptr[i + 1]);
    int k = k0;
    for (; k + 8 <= k1; k += 8) {
        int si[8]; float ai[8]; float4 vv[8];
        #pragma unroll
        for (int u = 0; u < 8; u++) si[u] = __ldg(&g_esrc[k + u]);
        #pragma unroll
        for (int u = 0; u < 8; u++) ai[u] = __ldg(&g_eea[k + u]);
        #pragma unroll
        for (int u = 0; u < 8; u++)
            vv[u] = ldhb4(g_hb + (size_t)si[u] * HH + c);
        #pragma unroll
        for (int u = 0; u < 8; u++) {
            acc.x += fmaxf(vv[u].x + fmaf(ai[u], ew.x, eb.x), 0.0f);
            acc.y += fmaxf(vv[u].y + fmaf(ai[u], ew.y, eb.y), 0.0f);
            acc.z += fmaxf(vv[u].z + fmaf(ai[u], ew.z, eb.z), 0.0f);
            acc.w += fmaxf(vv[u].w + fmaf(ai[u], ew.w, eb.w), 0.0f);
        }
    }
    for (; k < k1; k++) {
        int src = __ldg(&g_esrc[k]);
        float ea = __ldg(&g_eea[k]);
        float4 sv = ldhb4(g_hb + (size_t)src * HH + c);
        acc.x += fmaxf(sv.x + fmaf(ea, ew.x, eb.x), 0.0f);
        acc.y += fmaxf(sv.y + fmaf(ea, ew.y, eb.y), 0.0f);
        acc.z += fmaxf(sv.z + fmaf(ea, ew.z, eb.z), 0.0f);
        acc.w += fmaxf(sv.w + fmaf(ea, ew.w, eb.w), 0.0f);
    }
    *(uint2*)(g_aggrb + (size_t)i * HH + c) = pack_bf16x4(acc);
}

// ---------------------------------------------------------------------------
// Fused MLP: h = act2( relu(A@W1 + b1) @ W2 + b2 ) in ONE kernel.
// Phase 1: A (g_aggrb) @ W1 -> z (bias+relu) stored bf16 in smem sZ.
// Phase 2: sZ @ W2, epilogue bias+BN+relu -> OUTK (1: g_hb, 2: pool red).
// 8 warps (2x4), warp tile 64x32, mma m16n8k16, BK=16 chunks.
// smem: sA 6KB + sW 6KB + sZ 34KB = 47KB static -> 2 CTA/SM.
#define SWH 24    // A/W chunk stride in halves
#define SZS 136   // z tile stride in halves (conflict-free frag reads)
template <int OUTK, int L>
__global__ void __launch_bounds__(256, 2)
mlp_fused_kernel(const float* __restrict__ b1,
                 const float* __restrict__ b2,
                 const float* __restrict__ bn_g,
                 const float* __restrict__ bn_b,
                 const float* __restrict__ bn_m,
                 const float* __restrict__ bn_v,
                 const void* __restrict__ batch_raw,
                 int M) {
    const __nv_bfloat16* A  = g_aggrb;
    const __nv_bfloat16* W1 = g_Wt + (2 * L + 0) * (HH * HH);
    const __nv_bfloat16* W2 = g_Wt + (2 * L + 1) * (HH * HH);

    __shared__ __nv_bfloat16 sA[128 * SWH];   // 6144 B
    __shared__ __nv_bfloat16 sW[128 * SWH];   // 6144 B
    __shared__ __nv_bfloat16 sZ[128 * SZS];   // 34816 B

    int tid = threadIdx.x;
    int lane = tid & 31;
    int wid = tid >> 5;
    int g = lane >> 2;
    int tig = lane & 3;
    int wr = wid >> 2;
    int wc = wid & 3;
    int row0 = blockIdx.x * 128;

    int fr = tid >> 1;            // fill row/col (0..127)
    int fo = (tid & 1) * 8;       // half offset (0 or 8)

    float d[4][4][4];
    #pragma unroll
    for (int i = 0; i < 4; i++)
        #pragma unroll
        for (int j = 0; j < 4; j++)
            #pragma unroll
            for (int r = 0; r < 4; r++) d[i][j][r] = 0.0f;

    // ------------------ phase 1: A @ W1 ------------------
    for (int k0 = 0; k0 < HH; k0 += 16) {
        __syncthreads();
        {
            uint4 v = *(const uint4*)(W1 + (size_t)fr * HH + k0 + fo);
            *(uint2*)(sW + fr * SWH + fo)     = make_uint2(v.x, v.y);
            *(uint2*)(sW + fr * SWH + fo + 4) = make_uint2(v.z, v.w);
        }
        {
            int grow = row0 + fr;
            uint4 v = (grow < M)
                ? *(const uint4*)(A + (size_t)grow * HH + k0 + fo)
                : make_uint4(0u, 0u, 0u, 0u);
            *(uint2*)(sA + fr * SWH + fo)     = make_uint2(v.x, v.y);
            *(uint2*)(sA + fr * SWH + fo + 4) = make_uint2(v.z, v.w);
        }
        __syncthreads();

        u32 bf[4][2];
        #pragma unroll
        for (int nt = 0; nt < 4; nt++) {
            int cc = wc * 32 + nt * 8 + g;
            bf[nt][0] = *(const u32*)(sW + cc * SWH + 2 * tig);
            bf[nt][1] = *(const u32*)(sW + cc * SWH + 2 * tig + 8);
        }
        #pragma unroll
        for (int mt = 0; mt < 4; mt++) {
            int rr = wr * 64 + mt * 16 + g;
            u32 a[4];
            a[0] = *(const u32*)(sA + rr * SWH + 2 * tig);
            a[1] = *(const u32*)(sA + (rr + 8) * SWH + 2 * tig);
            a[2] = *(const u32*)(sA + rr * SWH + 2 * tig + 8);
            a[3] = *(const u32*)(sA + (rr + 8) * SWH + 2 * tig + 8);
            #pragma unroll
            for (int nt = 0; nt < 4; nt++)
                mma_bf16(d[mt][nt], a, bf[nt]);
        }
    }

    // epilogue 1: z = relu(d + b1) -> sZ (bf16), reset d
    #pragma unroll
    for (int nt = 0; nt < 4; nt++) {
        int c = wc * 32 + nt * 8 + 2 * tig;
        float2 bb = *(const float2*)(b1 + c);
        #pragma unroll
        for (int mt = 0; mt < 4; mt++) {
            int r0 = wr * 64 + mt * 16 + g;
            float z0 = fmaxf(d[mt][nt][0] + bb.x, 0.0f);
            float z1 = fmaxf(d[mt][nt][1] + bb.y, 0.0f);
            float z2 = fmaxf(d[mt][nt][2] + bb.x, 0.0f);
            float z3 = fmaxf(d[mt][nt][3] + bb.y, 0.0f);
            *(__nv_bfloat162*)(sZ + r0 * SZS + c) = __floats2bfloat162_rn(z0, z1);
            *(__nv_bfloat162*)(sZ + (r0 + 8) * SZS + c) = __floats2bfloat162_rn(z2, z3);
            d[mt][nt][0] = 0.0f; d[mt][nt][1] = 0.0f;
            d[mt][nt][2] = 0.0f; d[mt][nt][3] = 0.0f;
        }
    }

    // ------------------ phase 2: sZ @ W2 ------------------
    for (int k0 = 0; k0 < HH; k0 += 16) {
        __syncthreads();   // 1st iter: sZ complete; later: sW consumed
        {
            uint4 v = *(const uint4*)(W2 + (size_t)fr * HH + k0 + fo);
            *(uint2*)(sW + fr * SWH + fo)     = make_uint2(v.x, v.y);
            *(uint2*)(sW + fr * SWH + fo + 4) = make_uint2(v.z, v.w);
        }
        __syncthreads();

        u32 bf[4][2];
        #pragma unroll
        for (int nt = 0; nt < 4; nt++) {
            int cc = wc * 32 + nt * 8 + g;
            bf[nt][0] = *(const u32*)(sW + cc * SWH + 2 * tig);
            bf[nt][1] = *(const u32*)(sW + cc * SWH + 2 * tig + 8);
        }
        #pragma unroll
        for (int mt = 0; mt < 4; mt++) {
            int rr = wr * 64 + mt * 16 + g;
            u32 a[4];
            a[0] = *(const u32*)(sZ + rr * SZS + k0 + 2 * tig);
            a[1] = *(const u32*)(sZ + (rr + 8) * SZS + k0 + 2 * tig);
            a[2] = *(const u32*)(sZ + rr * SZS + k0 + 2 * tig + 8);
            a[3] = *(const u32*)(sZ + (rr + 8) * SZS + k0 + 2 * tig + 8);
            #pragma unroll
            for (int nt = 0; nt < 4; nt++)
                mma_bf16(d[mt][nt], a, bf[nt]);
        }
    }

    // epilogue 2: bias + BN + relu -> OUTK
    float2 bb[4], ssv[4], ttv[4];
    #pragma unroll
    for (int nt = 0; nt < 4; nt++) {
        int c = wc * 32 + nt * 8 + 2 * tig;
        bb[nt] = *(const float2*)(b2 + c);
        float2 bv = *(const float2*)(bn_v + c);
        float2 bg = *(const float2*)(bn_g + c);
        float2 bm = *(const float2*)(bn_m + c);
        float2 bbeta = *(const float2*)(bn_b + c);
        float i0 = rsqrtf(fabsf(bv.x) + 1e-5f);
        float i1 = rsqrtf(fabsf(bv.y) + 1e-5f);
        ssv[nt].x = bg.x * i0;
        ssv[nt].y = bg.y * i1;
        ttv[nt].x = bbeta.x - bm.x * ssv[nt].x;
        ttv[nt].y = bbeta.y - bm.y * ssv[nt].y;
    }

    #pragma unroll
    for (int mt = 0; mt < 4; mt++) {
        int r0 = row0 + wr * 64 + mt * 16 + g;
        int r1 = r0 + 8;
        long long b0 = 0, b1i = 0;
        if (OUTK == 2) {
            if (g_idx64) {
                if (r0 < M) b0  = __ldg((const long long*)batch_raw + r0);
                if (r1 < M) b1i = __ldg((const long long*)batch_raw + r1);
            } else {
                if (r0 < M) b0  = __ldg((const int*)batch_raw + r0);
                if (r1 < M) b1i = __ldg((const int*)batch_raw + r1);
            }
        }
        #pragma unroll
        for (int nt = 0; nt < 4; nt++) {
            int c = wc * 32 + nt * 8 + 2 * tig;
            float z0 = fmaf(d[mt][nt][0] + bb[nt].x, ssv[nt].x, ttv[nt].x);
            float z1 = fmaf(d[mt][nt][1] + bb[nt].y, ssv[nt].y, ttv[nt].y);
            float z2 = fmaf(d[mt][nt][2] + bb[nt].x, ssv[nt].x, ttv[nt].x);
            float z3 = fmaf(d[mt][nt][3] + bb[nt].y, ssv[nt].y, ttv[nt].y);
            z0 = fmaxf(z0, 0.0f); z1 = fmaxf(z1, 0.0f);
            z2 = fmaxf(z2, 0.0f); z3 = fmaxf(z3, 0.0f);
            if (OUTK == 2) {
                if (r0 < M && (unsigned long long)b0 < (unsigned long long)GG)
                    red_add_v2(g_pool + (size_t)b0 * HH + c, z0, z1);
                if (r1 < M && (unsigned long long)b1i < (unsigned long long)GG)
                    red_add_v2(g_pool + (size_t)b1i * HH + c, z2, z3);
            } else {
                if (r0 < M)
                    *(__nv_bfloat162*)(g_hb + (size_t)r0 * HH + c) =
                        __floats2bfloat162_rn(z0, z1);
                if (r1 < M)
                    *(__nv_bfloat162*)(g_hb + (size_t)r1 * HH + c) =
                        __floats2bfloat162_rn(z2, z3);
            }
        }
    }
}

// ---------------------------------------------------------------------------
__global__ void cnt_kernel(const void* __restrict__ batch_raw, int n) {
    int i = blockIdx.x * blockDim.x + threadIdx.x;
    if (i >= n) return;
    long long b;
    if (g_idx64) b = __ldg((const long long*)batch_raw + i);
    else         b = __ldg((const int*)batch_raw + i);
    if ((unsigned long long)b < (unsigned long long)GG)
        atomicAdd(&g_cnt[b], 1.0f);
}

// ---------------------------------------------------------------------------
// Classifier (single block): g=pool/cnt; st=relu(g@w1+b1); out=sigmoid(st@w2+b2)
__global__ void classifier_kernel(const float* __restrict__ cls_w1,
                                  const float* __restrict__ cls_b1,
                                  const float* __restrict__ cls_w2,
                                  const float* __restrict__ cls_b2,
                                  float* __restrict__ out) {
    __shared__ float sg[GG * HH];   // 32 KB
    int tid = threadIdx.x;          // 256
    for (int i = tid; i < GG * HH; i += 256) {
        float cnt = g_cnt[i >> 7];
        sg[i] = g_pool[i] / fmaxf(cnt, 1.0f);
    }
    __syncthreads();
    for (int e = tid; e < GG * 64; e += 256) {
        int gi = e >> 6;
        int m  = e & 63;
        float s = cls_b1[m];
        #pragma unroll 8
        for (int k = 0; k < HH; k++)
            s = fmaf(sg[gi * HH + k], cls_w1[k * 64 + m], s);
        g_st[e] = fmaxf(s, 0.0f);
    }
    __syncthreads();   // global writes by block visible after sync
    if (tid < GG) {
        float s = cls_b2[0];
        #pragma unroll 8
        for (int m = 0; m < 64; m++)
            s = fmaf(g_st[tid * 64 + m], cls_w2[m], s);
        out[tid] = 1.0f / (1.0f + expf(-s));
    }
}

// ---------------------------------------------------------------------------
extern "C" void kernel_launch(void* const* d_in, const int* in_sizes, int n_in,
                              void* d_out, int out_size) {
    const float *x, *edge_attr, *enc_w, *enc_b, *edge_w, *edge_b, *eps;
    const float *mlp_w1, *mlp_b1, *mlp_w2, *mlp_b2;
    const float *bn_gamma, *bn_beta, *bn_mean, *bn_var;
    const float *cls_w1, *cls_b1, *cls_w2, *cls_b2;
    const void *edge_index, *batch;
    int n, E;

    if (in_sizes[1] > 1000) {
        x          = (const float*)d_in[0];
        edge_index = d_in[1];
        edge_attr  = (const float*)d_in[2];
        batch      = d_in[3];
        enc_w      = (const float*)d_in[4];
        enc_b      = (const float*)d_in[5];
        edge_w     = (const float*)d_in[6];
        edge_b     = (const float*)d_in[7];
        eps        = (const float*)d_in[8];
        mlp_w1     = (const float*)d_in[9];
        mlp_b1     = (const float*)d_in[10];
        mlp_w2     = (const float*)d_in[11];
        mlp_b2     = (const float*)d_in[12];
        bn_gamma   = (const float*)d_in[13];
        bn_beta    = (const float*)d_in[14];
        bn_mean    = (const float*)d_in[15];
        bn_var     = (const float*)d_in[16];
        cls_w1     = (const float*)d_in[17];
        cls_b1     = (const float*)d_in[18];
        cls_w2     = (const float*)d_in[19];
        cls_b2     = (const float*)d_in[20];
        n = in_sizes[0];
        E = in_sizes[2];
    } else {
        batch      = d_in[0];
        bn_beta    = (const float*)d_in[1];
        bn_gamma   = (const float*)d_in[2];
        bn_mean    = (const float*)d_in[3];
        bn_var     = (const float*)d_in[4];
        cls_b1     = (const float*)d_in[5];
        cls_b2     = (const float*)d_in[6];
        cls_w1     = (const float*)d_in[7];
        cls_w2     = (const float*)d_in[8];
        edge_attr  = (const float*)d_in[9];
        edge_b     = (const float*)d_in[10];
        edge_index = d_in[11];
        edge_w     = (const float*)d_in[12];
        enc_b      = (const float*)d_in[13];
        enc_w      = (const float*)d_in[14];
        eps        = (const float*)d_in[15];
        mlp_b1     = (const float*)d_in[16];
        mlp_b2     = (const float*)d_in[17];
        mlp_w1     = (const float*)d_in[18];
        mlp_w2     = (const float*)d_in[19];
        x          = (const float*)d_in[20];
        n = in_sizes[20];
        E = in_sizes[9];
    }
    float* out = (float*)d_out;
    if (E > EE_MAX) E = EE_MAX;

    int nblk = (n + 255) / 256;

    // 0) init
    detect_kernel<<<1, 32>>>(edge_index, n);
    zero_misc_kernel<<<nblk, 256>>>(n);
    presplit_kernel<<<(2 * HH * HH + 255) / 256, 256>>>(mlp_w1, mlp_w2);

    // 1) CSR build
    csr_count_kernel<<<(E + 255) / 256, 256>>>(edge_index, E, n);
    blocksum_kernel<<<nblk, 256>>>(n);
    scan_bsum_kernel<<<1, 512>>>(nblk);
    rowptr_kernel<<<nblk, 256>>>(n, E);
    csr_fill_kernel<<<(E + 255) / 256, 256>>>(edge_index, edge_attr, E, n);

    // 2) layers (fused MLP: one kernel per layer)
    int gemm_blocks = (n + 127) / 128;
    int agg_blocks = (n * 32 + 255) / 256;

    aggregate_l0_kernel<<<agg_blocks, 256>>>(x, enc_w, enc_b, edge_w, edge_b,
                                             eps, n);
    mlp_fused_kernel<1, 0><<<gemm_blocks, 256>>>(
        mlp_b1, mlp_b2, bn_gamma, bn_beta, bn_mean, bn_var, nullptr, n);

    aggregate_kernel<<<agg_blocks, 256>>>(edge_w, edge_b, eps + 1, n);
    mlp_fused_kernel<2, 1><<<gemm_blocks, 256>>>(
        mlp_b1 + HH, mlp_b2 + HH, bn_gamma + HH, bn_beta + HH,
        bn_mean + HH, bn_var + HH, batch, n);

    // 3) counts + classifier
    cnt_kernel<<<nblk, 256>>>(batch, n);
    classifier_kernel<<<1, 256>>>(cls_w1, cls_b1, cls_w2, cls_b2, out);
}